// round 7
// baseline (speedup 1.0000x reference)
#include <cuda_runtime.h>
#include <cuda_bf16.h>
#include <math.h>
#include <cstdint>

// ================= helpers =================
__device__ __forceinline__ uint32_t smem_u32(const void* p) {
    uint32_t a;
    asm("{ .reg .u64 t; cvta.to.shared.u64 t, %1; cvt.u32.u64 %0, t; }" : "=r"(a) : "l"(p));
    return a;
}

#define CP_ASYNC16(dst, src) \
    asm volatile("cp.async.cg.shared.global [%0], [%1], 16;" :: "r"(dst), "l"(src))
#define CP_COMMIT() asm volatile("cp.async.commit_group;" ::: "memory")
#define CP_WAIT1()  asm volatile("cp.async.wait_group 1;" ::: "memory")
#define CP_WAIT0()  asm volatile("cp.async.wait_group 0;" ::: "memory")

#define LDSM_X4(r, addr) \
    asm volatile("ldmatrix.sync.aligned.m8n8.x4.shared.b16 {%0,%1,%2,%3}, [%4];" \
        : "=r"((r)[0]), "=r"((r)[1]), "=r"((r)[2]), "=r"((r)[3]) : "r"(addr))
#define LDSM_X2(r, addr) \
    asm volatile("ldmatrix.sync.aligned.m8n8.x2.shared.b16 {%0,%1}, [%2];" \
        : "=r"((r)[0]), "=r"((r)[1]) : "r"(addr))
#define MMA16816(d, a, b) \
    asm volatile("mma.sync.aligned.m16n8k16.row.col.f32.bf16.bf16.f32 " \
        "{%0,%1,%2,%3}, {%4,%5,%6,%7}, {%8,%9}, {%0,%1,%2,%3};" \
        : "+f"((d)[0]), "+f"((d)[1]), "+f"((d)[2]), "+f"((d)[3]) \
        : "r"((a)[0]), "r"((a)[1]), "r"((a)[2]), "r"((a)[3]), "r"((b)[0]), "r"((b)[1]))

// ================= scratch (no allocations allowed) =================
__device__ float g_Q[4096 * 2048];
__device__ float g_K[4096 * 512];
__device__ float g_V[4096 * 512];
__device__ float g_ctx[4096 * 2048];

__device__ __nv_bfloat16 g_xh[4096 * 2048];
__device__ __nv_bfloat16 g_xl[4096 * 2048];
__device__ __nv_bfloat16 g_wqh[2048 * 2048];
__device__ __nv_bfloat16 g_wql[2048 * 2048];
__device__ __nv_bfloat16 g_wkh[512 * 2048];
__device__ __nv_bfloat16 g_wkl[512 * 2048];
__device__ __nv_bfloat16 g_wvh[512 * 2048];
__device__ __nv_bfloat16 g_wvl[512 * 2048];
__device__ __nv_bfloat16 g_woh[2048 * 2048];
__device__ __nv_bfloat16 g_wol[2048 * 2048];
__device__ __nv_bfloat16 g_ch[4096 * 2048];
__device__ __nv_bfloat16 g_cl[4096 * 2048];

// ================= fp32 -> bf16 hi/lo split =================
__global__ __launch_bounds__(256) void split_bf16(const float* __restrict__ in,
                                                  __nv_bfloat16* __restrict__ hi,
                                                  __nv_bfloat16* __restrict__ lo,
                                                  int n4)
{
    int i = blockIdx.x * 256 + threadIdx.x;
    if (i >= n4) return;
    float4 v = ((const float4*)in)[i];
    __nv_bfloat16 h0 = __float2bfloat16(v.x);
    __nv_bfloat16 h1 = __float2bfloat16(v.y);
    __nv_bfloat16 h2 = __float2bfloat16(v.z);
    __nv_bfloat16 h3 = __float2bfloat16(v.w);
    __nv_bfloat16 l0 = __float2bfloat16(v.x - __bfloat162float(h0));
    __nv_bfloat16 l1 = __float2bfloat16(v.y - __bfloat162float(h1));
    __nv_bfloat16 l2 = __float2bfloat16(v.z - __bfloat162float(h2));
    __nv_bfloat16 l3 = __float2bfloat16(v.w - __bfloat162float(h3));
    ((__nv_bfloat162*)hi)[2 * i]     = __nv_bfloat162(h0, h1);
    ((__nv_bfloat162*)hi)[2 * i + 1] = __nv_bfloat162(h2, h3);
    ((__nv_bfloat162*)lo)[2 * i]     = __nv_bfloat162(l0, l1);
    ((__nv_bfloat162*)lo)[2 * i + 1] = __nv_bfloat162(l2, l3);
}

// ================= mma.sync split-bf16 GEMM: C = A[M,K] * B[N,K]^T =================
// CTA 128x128, 8 warps (4 x 2), warp tile 32x64. K-chunk 32, cp.async double buffer.
// smem tile row = 32 bf16 (64B) padded to 80B -> conflict-free ldmatrix.
#define TILE_B  (128 * 80)          // one operand tile (bytes)
#define BUF_B   (4 * TILE_B)        // Ah, Al, Bh, Bl
#define GEMM_SMEM (2 * BUF_B)       // double buffered = 81920

__global__ __launch_bounds__(256, 2)
void gemm_mma(const __nv_bfloat16* __restrict__ Ah, const __nv_bfloat16* __restrict__ Al,
              const __nv_bfloat16* __restrict__ Bh, const __nv_bfloat16* __restrict__ Bl,
              float* __restrict__ C, int Kdim, int ldc)
{
    extern __shared__ char sm[];
    const uint32_t sbase = smem_u32(sm);

    const int tid  = threadIdx.x;
    const int wid  = tid >> 5;
    const int lane = tid & 31;
    const int rowC = blockIdx.y * 128;
    const int colC = blockIdx.x * 128;

    // ---- loader mapping: 4 operand tiles x 64 threads ----
    const int t  = tid >> 6;       // 0:Ah 1:Al 2:Bh 3:Bl
    const int ln = tid & 63;
    const __nv_bfloat16* gsrc = (t == 0) ? Ah : (t == 1) ? Al : (t == 2) ? Bh : Bl;
    const int rbase = (t < 2) ? rowC : colC;

    const int NC = Kdim >> 5;      // chunks of 32

    // prologue: chunk 0
    {
        const int kc = 0;
        const uint32_t dstT = sbase + (uint32_t)t * TILE_B;
#pragma unroll
        for (int rr = 0; rr < 2; rr++) {
            int row = ln + (rr << 6);
            const char* src = (const char*)(gsrc + (size_t)(rbase + row) * Kdim + kc);
            uint32_t dst = dstT + (uint32_t)row * 80u;
#pragma unroll
            for (int cc = 0; cc < 4; cc++)
                CP_ASYNC16(dst + cc * 16, src + cc * 16);
        }
    }
    CP_COMMIT();

    const int warp_m = wid & 3;    // 0..3 -> 32 rows
    const int warp_n = wid >> 2;   // 0..1 -> 64 cols

    float acc[2][8][4];
#pragma unroll
    for (int mf = 0; mf < 2; mf++)
#pragma unroll
        for (int j = 0; j < 8; j++)
#pragma unroll
            for (int q = 0; q < 4; q++) acc[mf][j][q] = 0.f;

    for (int c = 0; c < NC; c++) {
        if (c + 1 < NC) {
            const int kc = (c + 1) << 5;
            const uint32_t dstT = sbase + (uint32_t)((c + 1) & 1) * BUF_B + (uint32_t)t * TILE_B;
#pragma unroll
            for (int rr = 0; rr < 2; rr++) {
                int row = ln + (rr << 6);
                const char* src = (const char*)(gsrc + (size_t)(rbase + row) * Kdim + kc);
                uint32_t dst = dstT + (uint32_t)row * 80u;
#pragma unroll
                for (int cc = 0; cc < 4; cc++)
                    CP_ASYNC16(dst + cc * 16, src + cc * 16);
            }
            CP_COMMIT();
            CP_WAIT1();
        } else {
            CP_WAIT0();
        }
        __syncthreads();

        const uint32_t buf = sbase + (uint32_t)(c & 1) * BUF_B;
        const uint32_t sAh = buf;
        const uint32_t sAl = buf + TILE_B;
        const uint32_t sBh = buf + 2 * TILE_B;
        const uint32_t sBl = buf + 3 * TILE_B;

#pragma unroll
        for (int ks = 0; ks < 2; ks++) {
            const uint32_t kb = (uint32_t)(ks * 32);   // 16 bf16 = 32 bytes

            uint32_t a_h[2][4], a_l[2][4];
#pragma unroll
            for (int mf = 0; mf < 2; mf++) {
                uint32_t row = (uint32_t)(warp_m * 32 + mf * 16 + (lane & 15));
                uint32_t col = (uint32_t)((lane >> 4) * 16) + kb;
                LDSM_X4(a_h[mf], sAh + row * 80u + col);
                LDSM_X4(a_l[mf], sAl + row * 80u + col);
            }
#pragma unroll
            for (int j = 0; j < 8; j++) {
                uint32_t nrow = (uint32_t)(warp_n * 64 + j * 8 + (lane & 7));
                uint32_t col  = (uint32_t)(((lane >> 3) & 1) * 16) + kb;
                uint32_t b_h[2], b_l[2];
                LDSM_X2(b_h, sBh + nrow * 80u + col);
                LDSM_X2(b_l, sBl + nrow * 80u + col);
#pragma unroll
                for (int mf = 0; mf < 2; mf++) {
                    MMA16816(acc[mf][j], a_h[mf], b_h);
                    MMA16816(acc[mf][j], a_h[mf], b_l);
                    MMA16816(acc[mf][j], a_l[mf], b_h);
                }
            }
        }
        __syncthreads();
    }

    // ---- epilogue: fp32 store ----
#pragma unroll
    for (int mf = 0; mf < 2; mf++) {
#pragma unroll
        for (int j = 0; j < 8; j++) {
            int r0 = rowC + warp_m * 32 + mf * 16 + (lane >> 2);
            int cc = colC + warp_n * 64 + j * 8 + (lane & 3) * 2;
            *(float2*)(C + (size_t)r0 * ldc + cc)       = make_float2(acc[mf][j][0], acc[mf][j][1]);
            *(float2*)(C + (size_t)(r0 + 8) * ldc + cc) = make_float2(acc[mf][j][2], acc[mf][j][3]);
        }
    }
}

// ================= RoPE (in-place on Q or K) =================
__global__ __launch_bounds__(256) void rope_kernel(float* __restrict__ data,
                                                   const int* __restrict__ positions,
                                                   int heads)
{
    int idx = blockIdx.x * 256 + threadIdx.x;
    int j = idx & 63;
    int row = idx >> 6;
    int bt = row / heads;
    float pos = (float)positions[bt];
    float inv_freq = powf(10000.0f, -(float)j * (1.0f / 64.0f));
    float ang = pos * inv_freq;
    float s, c;
    sincosf(ang, &s, &c);
    float* p = data + (size_t)row * 128;
    float x1 = p[j], x2 = p[j + 64];
    p[j]      = x1 * c - x2 * s;
    p[j + 64] = x1 * s + x2 * c;
}

// ================= flash attention (causal, GQA 4:1) =================
#define FA_SMEM ((128 * 64 + 128 * 64 + 64 * 128 + 64 * 65) * 4)

__global__ __launch_bounds__(256) void flash_attn(const float* __restrict__ Q,
                                                  const float* __restrict__ K,
                                                  const float* __restrict__ V,
                                                  float* __restrict__ ctx)
{
    const int T = 2048, HD = 128;
    extern __shared__ float smf[];
    float* Qt = smf;
    float* Kt = Qt + 128 * 64;
    float* Vs = Kt + 128 * 64;
    float* Ps = Vs + 64 * 128;

    int qt = blockIdx.x, h = blockIdx.y, b = blockIdx.z;
    int kvh = h >> 2;
    int tid = threadIdx.x;
    int tx = tid & 15, ty = tid >> 4;

    const float* Qg = Q + ((size_t)(b * T + qt * 64)) * 2048 + h * HD;
    for (int i = tid; i < 64 * 32; i += 256) {
        int r = i >> 5;
        int c4 = (i & 31) << 2;
        float4 v = *(const float4*)(Qg + (size_t)r * 2048 + c4);
        int base = (((r >> 2) ^ ((c4 >> 2) & 15)) << 2) + (r & 3);
        Qt[(c4 + 0) * 64 + base] = v.x;
        Qt[(c4 + 1) * 64 + base] = v.y;
        Qt[(c4 + 2) * 64 + base] = v.z;
        Qt[(c4 + 3) * 64 + base] = v.w;
    }

    float m[4], l[4], o[4][8];
#pragma unroll
    for (int i = 0; i < 4; i++) {
        m[i] = -INFINITY; l[i] = 0.f;
#pragma unroll
        for (int d = 0; d < 8; d++) o[i][d] = 0.f;
    }

    const float scale = 0.08838834764831845f;

    for (int kt = 0; kt <= qt; kt++) {
        __syncthreads();
        const float* Kg = K + ((size_t)(b * T + kt * 64)) * 512 + kvh * HD;
        const float* Vg = V + ((size_t)(b * T + kt * 64)) * 512 + kvh * HD;
        for (int i = tid; i < 64 * 32; i += 256) {
            int r = i >> 5;
            int c4 = (i & 31) << 2;
            float4 kv = *(const float4*)(Kg + (size_t)r * 512 + c4);
            int base = (((r >> 2) ^ ((c4 >> 2) & 15)) << 2) + (r & 3);
            Kt[(c4 + 0) * 64 + base] = kv.x;
            Kt[(c4 + 1) * 64 + base] = kv.y;
            Kt[(c4 + 2) * 64 + base] = kv.z;
            Kt[(c4 + 3) * 64 + base] = kv.w;
            *(float4*)(Vs + r * 128 + c4) = *(const float4*)(Vg + (size_t)r * 512 + c4);
        }
        __syncthreads();

        float s[4][4];
#pragma unroll
        for (int i = 0; i < 4; i++)
#pragma unroll
            for (int j = 0; j < 4; j++) s[i][j] = 0.f;

#pragma unroll 4
        for (int k = 0; k < HD; k++) {
            int sw = (k >> 2) & 15;
            float4 a  = *(const float4*)&Qt[k * 64 + ((ty ^ sw) << 2)];
            float4 bb = *(const float4*)&Kt[k * 64 + ((tx ^ sw) << 2)];
            float av[4] = {a.x, a.y, a.z, a.w};
            float bv[4] = {bb.x, bb.y, bb.z, bb.w};
#pragma unroll
            for (int i = 0; i < 4; i++)
#pragma unroll
                for (int j = 0; j < 4; j++)
                    s[i][j] = fmaf(av[i], bv[j], s[i][j]);
        }

        if (kt == qt) {
#pragma unroll
            for (int i = 0; i < 4; i++)
#pragma unroll
                for (int j = 0; j < 4; j++) {
                    int qi = ty * 4 + i, kj = tx * 4 + j;
                    s[i][j] = (kj <= qi) ? s[i][j] * scale : -1e9f;
                }
        } else {
#pragma unroll
            for (int i = 0; i < 4; i++)
#pragma unroll
                for (int j = 0; j < 4; j++) s[i][j] *= scale;
        }

#pragma unroll
        for (int i = 0; i < 4; i++) {
            float mt = fmaxf(fmaxf(s[i][0], s[i][1]), fmaxf(s[i][2], s[i][3]));
#pragma unroll
            for (int off = 8; off >= 1; off >>= 1)
                mt = fmaxf(mt, __shfl_xor_sync(0xffffffffu, mt, off));
            float mnew = fmaxf(m[i], mt);
            float corr = __expf(m[i] - mnew);
            float rs = 0.f;
#pragma unroll
            for (int j = 0; j < 4; j++) {
                float p = __expf(s[i][j] - mnew);
                s[i][j] = p;
                rs += p;
            }
#pragma unroll
            for (int off = 8; off >= 1; off >>= 1)
                rs += __shfl_xor_sync(0xffffffffu, rs, off);
            l[i] = l[i] * corr + rs;
            m[i] = mnew;
#pragma unroll
            for (int d = 0; d < 8; d++) o[i][d] *= corr;
        }

#pragma unroll
        for (int i = 0; i < 4; i++)
#pragma unroll
            for (int j = 0; j < 4; j++)
                Ps[(ty * 4 + i) * 65 + tx * 4 + j] = s[i][j];
        __syncthreads();

#pragma unroll 8
        for (int j = 0; j < 64; j++) {
            float4 v0 = *(const float4*)(Vs + j * 128 + tx * 8);
            float4 v1 = *(const float4*)(Vs + j * 128 + tx * 8 + 4);
#pragma unroll
            for (int i = 0; i < 4; i++) {
                float p = Ps[(ty * 4 + i) * 65 + j];
                o[i][0] = fmaf(p, v0.x, o[i][0]);
                o[i][1] = fmaf(p, v0.y, o[i][1]);
                o[i][2] = fmaf(p, v0.z, o[i][2]);
                o[i][3] = fmaf(p, v0.w, o[i][3]);
                o[i][4] = fmaf(p, v1.x, o[i][4]);
                o[i][5] = fmaf(p, v1.y, o[i][5]);
                o[i][6] = fmaf(p, v1.z, o[i][6]);
                o[i][7] = fmaf(p, v1.w, o[i][7]);
            }
        }
    }

    float* Cg = ctx + ((size_t)(b * T + qt * 64)) * 2048 + h * HD;
#pragma unroll
    for (int i = 0; i < 4; i++) {
        float inv = 1.0f / l[i];
        int r = ty * 4 + i;
        *(float4*)(Cg + (size_t)r * 2048 + tx * 8) =
            make_float4(o[i][0] * inv, o[i][1] * inv, o[i][2] * inv, o[i][3] * inv);
        *(float4*)(Cg + (size_t)r * 2048 + tx * 8 + 4) =
            make_float4(o[i][4] * inv, o[i][5] * inv, o[i][6] * inv, o[i][7] * inv);
    }
}

// ================= launch =================
extern "C" void kernel_launch(void* const* d_in, const int* in_sizes, int n_in,
                              void* d_out, int out_size)
{
    const float* x   = (const float*)d_in[0];
    const int*   pos = (const int*)d_in[1];
    const float* wq  = (const float*)d_in[2];
    const float* wk  = (const float*)d_in[3];
    const float* wv  = (const float*)d_in[4];
    const float* wo  = (const float*)d_in[5];
    float* out = (float*)d_out;

    float *Qp, *Kp, *Vp, *Cp;
    cudaGetSymbolAddress((void**)&Qp, g_Q);
    cudaGetSymbolAddress((void**)&Kp, g_K);
    cudaGetSymbolAddress((void**)&Vp, g_V);
    cudaGetSymbolAddress((void**)&Cp, g_ctx);

    __nv_bfloat16 *xh, *xl, *wqh, *wql, *wkh, *wkl, *wvh, *wvl, *woh, *wol, *ch, *cl;
    cudaGetSymbolAddress((void**)&xh,  g_xh);  cudaGetSymbolAddress((void**)&xl,  g_xl);
    cudaGetSymbolAddress((void**)&wqh, g_wqh); cudaGetSymbolAddress((void**)&wql, g_wql);
    cudaGetSymbolAddress((void**)&wkh, g_wkh); cudaGetSymbolAddress((void**)&wkl, g_wkl);
    cudaGetSymbolAddress((void**)&wvh, g_wvh); cudaGetSymbolAddress((void**)&wvl, g_wvl);
    cudaGetSymbolAddress((void**)&woh, g_woh); cudaGetSymbolAddress((void**)&wol, g_wol);
    cudaGetSymbolAddress((void**)&ch,  g_ch);  cudaGetSymbolAddress((void**)&cl,  g_cl);

    cudaFuncSetAttribute(flash_attn, cudaFuncAttributeMaxDynamicSharedMemorySize, FA_SMEM);
    cudaFuncSetAttribute(gemm_mma, cudaFuncAttributeMaxDynamicSharedMemorySize, GEMM_SMEM);

    // bf16 hi/lo splits
    split_bf16<<<(4096 * 2048 / 4) / 256, 256>>>(x,  xh,  xl,  4096 * 2048 / 4);
    split_bf16<<<(2048 * 2048 / 4) / 256, 256>>>(wq, wqh, wql, 2048 * 2048 / 4);
    split_bf16<<<(512  * 2048 / 4) / 256, 256>>>(wk, wkh, wkl, 512 * 2048 / 4);
    split_bf16<<<(512  * 2048 / 4) / 256, 256>>>(wv, wvh, wvl, 512 * 2048 / 4);
    split_bf16<<<(2048 * 2048 / 4) / 256, 256>>>(wo, woh, wol, 2048 * 2048 / 4);

    // QKV projections on tensor cores (mma.sync)
    gemm_mma<<<dim3(16, 32), 256, GEMM_SMEM>>>(xh, xl, wqh, wql, Qp, 2048, 2048);
    gemm_mma<<<dim3(4, 32),  256, GEMM_SMEM>>>(xh, xl, wkh, wkl, Kp, 2048, 512);
    gemm_mma<<<dim3(4, 32),  256, GEMM_SMEM>>>(xh, xl, wvh, wvl, Vp, 2048, 512);

    // RoPE
    rope_kernel<<<(4096 * 16 * 64) / 256, 256>>>(Qp, pos, 16);
    rope_kernel<<<(4096 * 4 * 64) / 256, 256>>>(Kp, pos, 4);

    // causal GQA attention
    flash_attn<<<dim3(32, 16, 2), 256, FA_SMEM>>>(Qp, Kp, Vp, Cp);

    // O projection on tensor cores
    split_bf16<<<(4096 * 2048 / 4) / 256, 256>>>(Cp, ch, cl, 4096 * 2048 / 4);
    gemm_mma<<<dim3(16, 32), 256, GEMM_SMEM>>>(ch, cl, woh, wol, out, 2048, 2048);
}

// round 8
// speedup vs baseline: 1.4797x; 1.4797x over previous
#include <cuda_runtime.h>
#include <cuda_bf16.h>
#include <math.h>
#include <cstdint>

// ================= helpers =================
__device__ __forceinline__ uint32_t smem_u32(const void* p) {
    uint32_t a;
    asm("{ .reg .u64 t; cvta.to.shared.u64 t, %1; cvt.u32.u64 %0, t; }" : "=r"(a) : "l"(p));
    return a;
}

#define CP_ASYNC16(dst, src) \
    asm volatile("cp.async.cg.shared.global [%0], [%1], 16;" :: "r"(dst), "l"(src))
#define CP_COMMIT() asm volatile("cp.async.commit_group;" ::: "memory")
#define CP_WAIT2()  asm volatile("cp.async.wait_group 2;" ::: "memory")
#define CP_WAIT1()  asm volatile("cp.async.wait_group 1;" ::: "memory")
#define CP_WAIT0()  asm volatile("cp.async.wait_group 0;" ::: "memory")

#define LDSM_X4(r, addr) \
    asm volatile("ldmatrix.sync.aligned.m8n8.x4.shared.b16 {%0,%1,%2,%3}, [%4];" \
        : "=r"((r)[0]), "=r"((r)[1]), "=r"((r)[2]), "=r"((r)[3]) : "r"(addr))
#define MMA16816(d, a, b0, b1) \
    asm volatile("mma.sync.aligned.m16n8k16.row.col.f32.bf16.bf16.f32 " \
        "{%0,%1,%2,%3}, {%4,%5,%6,%7}, {%8,%9}, {%0,%1,%2,%3};" \
        : "+f"((d)[0]), "+f"((d)[1]), "+f"((d)[2]), "+f"((d)[3]) \
        : "r"((a)[0]), "r"((a)[1]), "r"((a)[2]), "r"((a)[3]), "r"(b0), "r"(b1))

// ================= scratch (no allocations allowed) =================
__device__ float g_Q[4096 * 2048];
__device__ float g_K[4096 * 512];
__device__ float g_V[4096 * 512];
__device__ float g_ctx[4096 * 2048];

__device__ __nv_bfloat16 g_xh[4096 * 2048];
__device__ __nv_bfloat16 g_xl[4096 * 2048];
__device__ __nv_bfloat16 g_wqh[2048 * 2048];
__device__ __nv_bfloat16 g_wql[2048 * 2048];
__device__ __nv_bfloat16 g_wkh[512 * 2048];
__device__ __nv_bfloat16 g_wkl[512 * 2048];
__device__ __nv_bfloat16 g_wvh[512 * 2048];
__device__ __nv_bfloat16 g_wvl[512 * 2048];
__device__ __nv_bfloat16 g_woh[2048 * 2048];
__device__ __nv_bfloat16 g_wol[2048 * 2048];
__device__ __nv_bfloat16 g_ch[4096 * 2048];
__device__ __nv_bfloat16 g_cl[4096 * 2048];

// ================= fp32 -> bf16 hi/lo split =================
__global__ __launch_bounds__(256) void split_bf16(const float* __restrict__ in,
                                                  __nv_bfloat16* __restrict__ hi,
                                                  __nv_bfloat16* __restrict__ lo,
                                                  int n4)
{
    int i = blockIdx.x * 256 + threadIdx.x;
    if (i >= n4) return;
    float4 v = ((const float4*)in)[i];
    __nv_bfloat16 h0 = __float2bfloat16(v.x);
    __nv_bfloat16 h1 = __float2bfloat16(v.y);
    __nv_bfloat16 h2 = __float2bfloat16(v.z);
    __nv_bfloat16 h3 = __float2bfloat16(v.w);
    __nv_bfloat16 l0 = __float2bfloat16(v.x - __bfloat162float(h0));
    __nv_bfloat16 l1 = __float2bfloat16(v.y - __bfloat162float(h1));
    __nv_bfloat16 l2 = __float2bfloat16(v.z - __bfloat162float(h2));
    __nv_bfloat16 l3 = __float2bfloat16(v.w - __bfloat162float(h3));
    ((__nv_bfloat162*)hi)[2 * i]     = __nv_bfloat162(h0, h1);
    ((__nv_bfloat162*)hi)[2 * i + 1] = __nv_bfloat162(h2, h3);
    ((__nv_bfloat162*)lo)[2 * i]     = __nv_bfloat162(l0, l1);
    ((__nv_bfloat162*)lo)[2 * i + 1] = __nv_bfloat162(l2, l3);
}

// ================= mma.sync split-bf16 GEMM core =================
// CTA 128x128, 8 warps (4 x 2), warp tile 32x64. K-chunk 32.
// 3-stage cp.async pipeline; smem row = 32 bf16 (64B) padded to 80B.
#define TILE_B  (128 * 80)
#define BUF_B   (4 * TILE_B)          // Ah, Al, Bh, Bl = 40960
#define NSTAGE  3
#define GEMM_SMEM (NSTAGE * BUF_B)    // 122880

__device__ __forceinline__ void gemm_body(
    const __nv_bfloat16* __restrict__ Ah, const __nv_bfloat16* __restrict__ Al,
    const __nv_bfloat16* __restrict__ Bh, const __nv_bfloat16* __restrict__ Bl,
    float* __restrict__ C, int Kdim, int ldc, int rowC, int colC, char* smptr)
{
    const uint32_t sbase = smem_u32(smptr);
    const int tid  = threadIdx.x;
    const int wid  = tid >> 5;
    const int lane = tid & 31;

    // loader mapping: 4 operand tiles x 64 threads
    const int t  = tid >> 6;          // 0:Ah 1:Al 2:Bh 3:Bl
    const int ln = tid & 63;
    const __nv_bfloat16* gsrc = (t == 0) ? Ah : (t == 1) ? Al : (t == 2) ? Bh : Bl;
    const int rbase = (t < 2) ? rowC : colC;

    const int NC = Kdim >> 5;

    // prologue: chunks 0 and 1
#pragma unroll
    for (int pc = 0; pc < 2; pc++) {
        const uint32_t dstT = sbase + (uint32_t)pc * BUF_B + (uint32_t)t * TILE_B;
        const int kc = pc << 5;
#pragma unroll
        for (int rr = 0; rr < 2; rr++) {
            int row = ln + (rr << 6);
            const char* src = (const char*)(gsrc + (size_t)(rbase + row) * Kdim + kc);
            uint32_t dst = dstT + (uint32_t)row * 80u;
#pragma unroll
            for (int cc = 0; cc < 4; cc++)
                CP_ASYNC16(dst + cc * 16, src + cc * 16);
        }
        CP_COMMIT();
    }

    const int warp_m = wid & 3;
    const int warp_n = wid >> 2;

    float acc[2][8][4];
#pragma unroll
    for (int mf = 0; mf < 2; mf++)
#pragma unroll
        for (int j = 0; j < 8; j++)
#pragma unroll
            for (int q = 0; q < 4; q++) acc[mf][j][q] = 0.f;

    for (int c = 0; c < NC; c++) {
        if (c + 2 < NC) {
            const int kc = (c + 2) << 5;
            const uint32_t dstT = sbase + (uint32_t)((c + 2) % NSTAGE) * BUF_B
                                        + (uint32_t)t * TILE_B;
#pragma unroll
            for (int rr = 0; rr < 2; rr++) {
                int row = ln + (rr << 6);
                const char* src = (const char*)(gsrc + (size_t)(rbase + row) * Kdim + kc);
                uint32_t dst = dstT + (uint32_t)row * 80u;
#pragma unroll
                for (int cc = 0; cc < 4; cc++)
                    CP_ASYNC16(dst + cc * 16, src + cc * 16);
            }
            CP_COMMIT();
            CP_WAIT2();
        } else if (c + 1 < NC) {
            CP_WAIT1();
        } else {
            CP_WAIT0();
        }
        __syncthreads();

        const uint32_t buf = sbase + (uint32_t)(c % NSTAGE) * BUF_B;
        const uint32_t sAh = buf;
        const uint32_t sAl = buf + TILE_B;
        const uint32_t sBh = buf + 2 * TILE_B;
        const uint32_t sBl = buf + 3 * TILE_B;

#pragma unroll
        for (int ks = 0; ks < 2; ks++) {
            const uint32_t kb = (uint32_t)(ks * 32);

            uint32_t a_h[2][4], a_l[2][4];
#pragma unroll
            for (int mf = 0; mf < 2; mf++) {
                uint32_t row = (uint32_t)(warp_m * 32 + mf * 16 + (lane & 15));
                uint32_t col = (uint32_t)((lane >> 4) * 16) + kb;
                LDSM_X4(a_h[mf], sAh + row * 80u + col);
                LDSM_X4(a_l[mf], sAl + row * 80u + col);
            }

            // B fragments: ldmatrix.x4 covers n16 x k16 (2 n8 tiles)
            const int l8  = lane & 7;
            const int grp = lane >> 3;
            const uint32_t brow_off = (uint32_t)(l8 + ((grp & 2) ? 8 : 0));
            const uint32_t bcol     = kb + ((grp & 1) ? 16u : 0u);
#pragma unroll
            for (int g = 0; g < 4; g++) {
                uint32_t nrow = (uint32_t)(warp_n * 64 + g * 16) + brow_off;
                uint32_t b_h[4], b_l[4];
                LDSM_X4(b_h, sBh + nrow * 80u + bcol);
                LDSM_X4(b_l, sBl + nrow * 80u + bcol);
#pragma unroll
                for (int mf = 0; mf < 2; mf++) {
                    MMA16816(acc[mf][2 * g],     a_h[mf], b_h[0], b_h[1]);
                    MMA16816(acc[mf][2 * g],     a_h[mf], b_l[0], b_l[1]);
                    MMA16816(acc[mf][2 * g],     a_l[mf], b_h[0], b_h[1]);
                    MMA16816(acc[mf][2 * g + 1], a_h[mf], b_h[2], b_h[3]);
                    MMA16816(acc[mf][2 * g + 1], a_h[mf], b_l[2], b_l[3]);
                    MMA16816(acc[mf][2 * g + 1], a_l[mf], b_h[2], b_h[3]);
                }
            }
        }
        __syncthreads();
    }

    // epilogue
#pragma unroll
    for (int mf = 0; mf < 2; mf++) {
#pragma unroll
        for (int j = 0; j < 8; j++) {
            int r0 = rowC + warp_m * 32 + mf * 16 + (lane >> 2);
            int cc = colC + warp_n * 64 + j * 8 + (lane & 3) * 2;
            *(float2*)(C + (size_t)r0 * ldc + cc)       = make_float2(acc[mf][j][0], acc[mf][j][1]);
            *(float2*)(C + (size_t)(r0 + 8) * ldc + cc) = make_float2(acc[mf][j][2], acc[mf][j][3]);
        }
    }
}

// fused QKV: grid = (24, 32). bx<16 -> Q, <20 -> K, else V
__global__ __launch_bounds__(256)
void gemm_qkv(const __nv_bfloat16* __restrict__ xh, const __nv_bfloat16* __restrict__ xl,
              const __nv_bfloat16* __restrict__ wqh, const __nv_bfloat16* __restrict__ wql,
              const __nv_bfloat16* __restrict__ wkh, const __nv_bfloat16* __restrict__ wkl,
              const __nv_bfloat16* __restrict__ wvh, const __nv_bfloat16* __restrict__ wvl,
              float* __restrict__ Qo, float* __restrict__ Ko, float* __restrict__ Vo)
{
    extern __shared__ char sm[];
    int bx = blockIdx.x;
    const __nv_bfloat16 *Bh, *Bl; float* C; int ldc, colC;
    if (bx < 16)      { Bh = wqh; Bl = wql; C = Qo; ldc = 2048; colC = bx * 128; }
    else if (bx < 20) { Bh = wkh; Bl = wkl; C = Ko; ldc = 512;  colC = (bx - 16) * 128; }
    else              { Bh = wvh; Bl = wvl; C = Vo; ldc = 512;  colC = (bx - 20) * 128; }
    gemm_body(xh, xl, Bh, Bl, C, 2048, ldc, blockIdx.y * 128, colC, sm);
}

__global__ __launch_bounds__(256)
void gemm_mma(const __nv_bfloat16* __restrict__ Ah, const __nv_bfloat16* __restrict__ Al,
              const __nv_bfloat16* __restrict__ Bh, const __nv_bfloat16* __restrict__ Bl,
              float* __restrict__ C, int Kdim, int ldc)
{
    extern __shared__ char sm[];
    gemm_body(Ah, Al, Bh, Bl, C, Kdim, ldc, blockIdx.y * 128, blockIdx.x * 128, sm);
}

// ================= RoPE (in-place on Q or K) =================
__global__ __launch_bounds__(256) void rope_kernel(float* __restrict__ data,
                                                   const int* __restrict__ positions,
                                                   int heads)
{
    int idx = blockIdx.x * 256 + threadIdx.x;
    int j = idx & 63;
    int row = idx >> 6;
    int bt = row / heads;
    float pos = (float)positions[bt];
    float inv_freq = powf(10000.0f, -(float)j * (1.0f / 64.0f));
    float ang = pos * inv_freq;
    float s, c;
    sincosf(ang, &s, &c);
    float* p = data + (size_t)row * 128;
    float x1 = p[j], x2 = p[j + 64];
    p[j]      = x1 * c - x2 * s;
    p[j + 64] = x1 * s + x2 * c;
}

// ================= flash attention (causal, GQA 4:1) =================
#define FA_SMEM ((128 * 64 + 128 * 64 + 64 * 128 + 64 * 65) * 4)

__global__ __launch_bounds__(256) void flash_attn(const float* __restrict__ Q,
                                                  const float* __restrict__ K,
                                                  const float* __restrict__ V,
                                                  float* __restrict__ ctx)
{
    const int T = 2048, HD = 128;
    extern __shared__ float smf[];
    float* Qt = smf;
    float* Kt = Qt + 128 * 64;
    float* Vs = Kt + 128 * 64;
    float* Ps = Vs + 64 * 128;

    int qt = blockIdx.x, h = blockIdx.y, b = blockIdx.z;
    int kvh = h >> 2;
    int tid = threadIdx.x;
    int tx = tid & 15, ty = tid >> 4;

    const float* Qg = Q + ((size_t)(b * T + qt * 64)) * 2048 + h * HD;
    for (int i = tid; i < 64 * 32; i += 256) {
        int r = i >> 5;
        int c4 = (i & 31) << 2;
        float4 v = *(const float4*)(Qg + (size_t)r * 2048 + c4);
        int base = (((r >> 2) ^ ((c4 >> 2) & 15)) << 2) + (r & 3);
        Qt[(c4 + 0) * 64 + base] = v.x;
        Qt[(c4 + 1) * 64 + base] = v.y;
        Qt[(c4 + 2) * 64 + base] = v.z;
        Qt[(c4 + 3) * 64 + base] = v.w;
    }

    float m[4], l[4], o[4][8];
#pragma unroll
    for (int i = 0; i < 4; i++) {
        m[i] = -INFINITY; l[i] = 0.f;
#pragma unroll
        for (int d = 0; d < 8; d++) o[i][d] = 0.f;
    }

    const float scale = 0.08838834764831845f;

    for (int kt = 0; kt <= qt; kt++) {
        __syncthreads();
        const float* Kg = K + ((size_t)(b * T + kt * 64)) * 512 + kvh * HD;
        const float* Vg = V + ((size_t)(b * T + kt * 64)) * 512 + kvh * HD;
        for (int i = tid; i < 64 * 32; i += 256) {
            int r = i >> 5;
            int c4 = (i & 31) << 2;
            float4 kv = *(const float4*)(Kg + (size_t)r * 512 + c4);
            int base = (((r >> 2) ^ ((c4 >> 2) & 15)) << 2) + (r & 3);
            Kt[(c4 + 0) * 64 + base] = kv.x;
            Kt[(c4 + 1) * 64 + base] = kv.y;
            Kt[(c4 + 2) * 64 + base] = kv.z;
            Kt[(c4 + 3) * 64 + base] = kv.w;
            *(float4*)(Vs + r * 128 + c4) = *(const float4*)(Vg + (size_t)r * 512 + c4);
        }
        __syncthreads();

        float s[4][4];
#pragma unroll
        for (int i = 0; i < 4; i++)
#pragma unroll
            for (int j = 0; j < 4; j++) s[i][j] = 0.f;

#pragma unroll 4
        for (int k = 0; k < HD; k++) {
            int sw = (k >> 2) & 15;
            float4 a  = *(const float4*)&Qt[k * 64 + ((ty ^ sw) << 2)];
            float4 bb = *(const float4*)&Kt[k * 64 + ((tx ^ sw) << 2)];
            float av[4] = {a.x, a.y, a.z, a.w};
            float bv[4] = {bb.x, bb.y, bb.z, bb.w};
#pragma unroll
            for (int i = 0; i < 4; i++)
#pragma unroll
                for (int j = 0; j < 4; j++)
                    s[i][j] = fmaf(av[i], bv[j], s[i][j]);
        }

        if (kt == qt) {
#pragma unroll
            for (int i = 0; i < 4; i++)
#pragma unroll
                for (int j = 0; j < 4; j++) {
                    int qi = ty * 4 + i, kj = tx * 4 + j;
                    s[i][j] = (kj <= qi) ? s[i][j] * scale : -1e9f;
                }
        } else {
#pragma unroll
            for (int i = 0; i < 4; i++)
#pragma unroll
                for (int j = 0; j < 4; j++) s[i][j] *= scale;
        }

#pragma unroll
        for (int i = 0; i < 4; i++) {
            float mt = fmaxf(fmaxf(s[i][0], s[i][1]), fmaxf(s[i][2], s[i][3]));
#pragma unroll
            for (int off = 8; off >= 1; off >>= 1)
                mt = fmaxf(mt, __shfl_xor_sync(0xffffffffu, mt, off));
            float mnew = fmaxf(m[i], mt);
            float corr = __expf(m[i] - mnew);
            float rs = 0.f;
#pragma unroll
            for (int j = 0; j < 4; j++) {
                float p = __expf(s[i][j] - mnew);
                s[i][j] = p;
                rs += p;
            }
#pragma unroll
            for (int off = 8; off >= 1; off >>= 1)
                rs += __shfl_xor_sync(0xffffffffu, rs, off);
            l[i] = l[i] * corr + rs;
            m[i] = mnew;
#pragma unroll
            for (int d = 0; d < 8; d++) o[i][d] *= corr;
        }

#pragma unroll
        for (int i = 0; i < 4; i++)
#pragma unroll
            for (int j = 0; j < 4; j++)
                Ps[(ty * 4 + i) * 65 + tx * 4 + j] = s[i][j];
        __syncthreads();

#pragma unroll 8
        for (int j = 0; j < 64; j++) {
            float4 v0 = *(const float4*)(Vs + j * 128 + tx * 8);
            float4 v1 = *(const float4*)(Vs + j * 128 + tx * 8 + 4);
#pragma unroll
            for (int i = 0; i < 4; i++) {
                float p = Ps[(ty * 4 + i) * 65 + j];
                o[i][0] = fmaf(p, v0.x, o[i][0]);
                o[i][1] = fmaf(p, v0.y, o[i][1]);
                o[i][2] = fmaf(p, v0.z, o[i][2]);
                o[i][3] = fmaf(p, v0.w, o[i][3]);
                o[i][4] = fmaf(p, v1.x, o[i][4]);
                o[i][5] = fmaf(p, v1.y, o[i][5]);
                o[i][6] = fmaf(p, v1.z, o[i][6]);
                o[i][7] = fmaf(p, v1.w, o[i][7]);
            }
        }
    }

    float* Cg = ctx + ((size_t)(b * T + qt * 64)) * 2048 + h * HD;
#pragma unroll
    for (int i = 0; i < 4; i++) {
        float inv = 1.0f / l[i];
        int r = ty * 4 + i;
        *(float4*)(Cg + (size_t)r * 2048 + tx * 8) =
            make_float4(o[i][0] * inv, o[i][1] * inv, o[i][2] * inv, o[i][3] * inv);
        *(float4*)(Cg + (size_t)r * 2048 + tx * 8 + 4) =
            make_float4(o[i][4] * inv, o[i][5] * inv, o[i][6] * inv, o[i][7] * inv);
    }
}

// ================= launch =================
extern "C" void kernel_launch(void* const* d_in, const int* in_sizes, int n_in,
                              void* d_out, int out_size)
{
    const float* x   = (const float*)d_in[0];
    const int*   pos = (const int*)d_in[1];
    const float* wq  = (const float*)d_in[2];
    const float* wk  = (const float*)d_in[3];
    const float* wv  = (const float*)d_in[4];
    const float* wo  = (const float*)d_in[5];
    float* out = (float*)d_out;

    float *Qp, *Kp, *Vp, *Cp;
    cudaGetSymbolAddress((void**)&Qp, g_Q);
    cudaGetSymbolAddress((void**)&Kp, g_K);
    cudaGetSymbolAddress((void**)&Vp, g_V);
    cudaGetSymbolAddress((void**)&Cp, g_ctx);

    __nv_bfloat16 *xh, *xl, *wqh, *wql, *wkh, *wkl, *wvh, *wvl, *woh, *wol, *ch, *cl;
    cudaGetSymbolAddress((void**)&xh,  g_xh);  cudaGetSymbolAddress((void**)&xl,  g_xl);
    cudaGetSymbolAddress((void**)&wqh, g_wqh); cudaGetSymbolAddress((void**)&wql, g_wql);
    cudaGetSymbolAddress((void**)&wkh, g_wkh); cudaGetSymbolAddress((void**)&wkl, g_wkl);
    cudaGetSymbolAddress((void**)&wvh, g_wvh); cudaGetSymbolAddress((void**)&wvl, g_wvl);
    cudaGetSymbolAddress((void**)&woh, g_woh); cudaGetSymbolAddress((void**)&wol, g_wol);
    cudaGetSymbolAddress((void**)&ch,  g_ch);  cudaGetSymbolAddress((void**)&cl,  g_cl);

    cudaFuncSetAttribute(flash_attn, cudaFuncAttributeMaxDynamicSharedMemorySize, FA_SMEM);
    cudaFuncSetAttribute(gemm_qkv, cudaFuncAttributeMaxDynamicSharedMemorySize, GEMM_SMEM);
    cudaFuncSetAttribute(gemm_mma, cudaFuncAttributeMaxDynamicSharedMemorySize, GEMM_SMEM);

    // bf16 hi/lo splits
    split_bf16<<<(4096 * 2048 / 4) / 256, 256>>>(x,  xh,  xl,  4096 * 2048 / 4);
    split_bf16<<<(2048 * 2048 / 4) / 256, 256>>>(wq, wqh, wql, 2048 * 2048 / 4);
    split_bf16<<<(512  * 2048 / 4) / 256, 256>>>(wk, wkh, wkl, 512 * 2048 / 4);
    split_bf16<<<(512  * 2048 / 4) / 256, 256>>>(wv, wvh, wvl, 512 * 2048 / 4);
    split_bf16<<<(2048 * 2048 / 4) / 256, 256>>>(wo, woh, wol, 2048 * 2048 / 4);

    // fused QKV projection on tensor cores (one 768-CTA launch)
    gemm_qkv<<<dim3(24, 32), 256, GEMM_SMEM>>>(xh, xl, wqh, wql, wkh, wkl, wvh, wvl,
                                               Qp, Kp, Vp);

    // RoPE
    rope_kernel<<<(4096 * 16 * 64) / 256, 256>>>(Qp, pos, 16);
    rope_kernel<<<(4096 * 4 * 64) / 256, 256>>>(Kp, pos, 4);

    // causal GQA attention
    flash_attn<<<dim3(32, 16, 2), 256, FA_SMEM>>>(Qp, Kp, Vp, Cp);

    // O projection on tensor cores
    split_bf16<<<(4096 * 2048 / 4) / 256, 256>>>(Cp, ch, cl, 4096 * 2048 / 4);
    gemm_mma<<<dim3(16, 32), 256, GEMM_SMEM>>>(ch, cl, woh, wol, out, 2048, 2048);
}

// round 9
// speedup vs baseline: 2.2102x; 1.4937x over previous
#include <cuda_runtime.h>
#include <cuda_bf16.h>
#include <math.h>
#include <cstdint>

// ================= helpers =================
__device__ __forceinline__ uint32_t smem_u32(const void* p) {
    uint32_t a;
    asm("{ .reg .u64 t; cvta.to.shared.u64 t, %1; cvt.u32.u64 %0, t; }" : "=r"(a) : "l"(p));
    return a;
}

#define CP_ASYNC16(dst, src) \
    asm volatile("cp.async.cg.shared.global [%0], [%1], 16;" :: "r"(dst), "l"(src))
#define CP_COMMIT() asm volatile("cp.async.commit_group;" ::: "memory")
#define CP_WAIT2()  asm volatile("cp.async.wait_group 2;" ::: "memory")
#define CP_WAIT1()  asm volatile("cp.async.wait_group 1;" ::: "memory")
#define CP_WAIT0()  asm volatile("cp.async.wait_group 0;" ::: "memory")

#define LDSM_X4(r, addr) \
    asm volatile("ldmatrix.sync.aligned.m8n8.x4.shared.b16 {%0,%1,%2,%3}, [%4];" \
        : "=r"((r)[0]), "=r"((r)[1]), "=r"((r)[2]), "=r"((r)[3]) : "r"(addr))
#define MMA16816(d, a, b0, b1) \
    asm volatile("mma.sync.aligned.m16n8k16.row.col.f32.bf16.bf16.f32 " \
        "{%0,%1,%2,%3}, {%4,%5,%6,%7}, {%8,%9}, {%0,%1,%2,%3};" \
        : "+f"((d)[0]), "+f"((d)[1]), "+f"((d)[2]), "+f"((d)[3]) \
        : "r"((a)[0]), "r"((a)[1]), "r"((a)[2]), "r"((a)[3]), "r"(b0), "r"(b1))

__device__ __forceinline__ uint32_t pack_bf2(float lo, float hi) {
    uint32_t r;
    asm("cvt.rn.bf16x2.f32 %0, %1, %2;" : "=r"(r) : "f"(hi), "f"(lo));
    return r;
}
__device__ __forceinline__ float bf_round(float x) {
    return __bfloat162float(__float2bfloat16(x));
}

// ================= scratch (no allocations allowed) =================
__device__ float g_Q[4096 * 2048];
__device__ float g_K[4096 * 512];
__device__ float g_V[4096 * 512];
__device__ float g_ctx[4096 * 2048];

__device__ __nv_bfloat16 g_xh[4096 * 2048];
__device__ __nv_bfloat16 g_xl[4096 * 2048];
__device__ __nv_bfloat16 g_wqh[2048 * 2048];
__device__ __nv_bfloat16 g_wql[2048 * 2048];
__device__ __nv_bfloat16 g_wkh[512 * 2048];
__device__ __nv_bfloat16 g_wkl[512 * 2048];
__device__ __nv_bfloat16 g_wvh[512 * 2048];
__device__ __nv_bfloat16 g_wvl[512 * 2048];
__device__ __nv_bfloat16 g_woh[2048 * 2048];
__device__ __nv_bfloat16 g_wol[2048 * 2048];
__device__ __nv_bfloat16 g_ch[4096 * 2048];
__device__ __nv_bfloat16 g_cl[4096 * 2048];

// attention operands (head-major)
__device__ __nv_bfloat16 g_qbh[2 * 16 * 2048 * 128];
__device__ __nv_bfloat16 g_qbl[2 * 16 * 2048 * 128];
__device__ __nv_bfloat16 g_kbh[2 * 4 * 2048 * 128];
__device__ __nv_bfloat16 g_kbl[2 * 4 * 2048 * 128];
__device__ __nv_bfloat16 g_vth[2 * 4 * 128 * 2048];   // V transposed [b][kvh][d][t]
__device__ __nv_bfloat16 g_vtl[2 * 4 * 128 * 2048];

// ================= fp32 -> bf16 hi/lo split =================
__global__ __launch_bounds__(256) void split_bf16(const float* __restrict__ in,
                                                  __nv_bfloat16* __restrict__ hi,
                                                  __nv_bfloat16* __restrict__ lo,
                                                  int n4)
{
    int i = blockIdx.x * 256 + threadIdx.x;
    if (i >= n4) return;
    float4 v = ((const float4*)in)[i];
    __nv_bfloat16 h0 = __float2bfloat16(v.x);
    __nv_bfloat16 h1 = __float2bfloat16(v.y);
    __nv_bfloat16 h2 = __float2bfloat16(v.z);
    __nv_bfloat16 h3 = __float2bfloat16(v.w);
    __nv_bfloat16 l0 = __float2bfloat16(v.x - __bfloat162float(h0));
    __nv_bfloat16 l1 = __float2bfloat16(v.y - __bfloat162float(h1));
    __nv_bfloat16 l2 = __float2bfloat16(v.z - __bfloat162float(h2));
    __nv_bfloat16 l3 = __float2bfloat16(v.w - __bfloat162float(h3));
    ((__nv_bfloat162*)hi)[2 * i]     = __nv_bfloat162(h0, h1);
    ((__nv_bfloat162*)hi)[2 * i + 1] = __nv_bfloat162(h2, h3);
    ((__nv_bfloat162*)lo)[2 * i]     = __nv_bfloat162(l0, l1);
    ((__nv_bfloat162*)lo)[2 * i + 1] = __nv_bfloat162(l2, l3);
}

// ================= mma.sync split-bf16 GEMM core (unchanged from R8) =================
#define TILE_B  (128 * 80)
#define BUF_B   (4 * TILE_B)
#define NSTAGE  3
#define GEMM_SMEM (NSTAGE * BUF_B)

__device__ __forceinline__ void gemm_body(
    const __nv_bfloat16* __restrict__ Ah, const __nv_bfloat16* __restrict__ Al,
    const __nv_bfloat16* __restrict__ Bh, const __nv_bfloat16* __restrict__ Bl,
    float* __restrict__ C, int Kdim, int ldc, int rowC, int colC, char* smptr)
{
    const uint32_t sbase = smem_u32(smptr);
    const int tid  = threadIdx.x;
    const int wid  = tid >> 5;
    const int lane = tid & 31;

    const int t  = tid >> 6;
    const int ln = tid & 63;
    const __nv_bfloat16* gsrc = (t == 0) ? Ah : (t == 1) ? Al : (t == 2) ? Bh : Bl;
    const int rbase = (t < 2) ? rowC : colC;

    const int NC = Kdim >> 5;

#pragma unroll
    for (int pc = 0; pc < 2; pc++) {
        const uint32_t dstT = sbase + (uint32_t)pc * BUF_B + (uint32_t)t * TILE_B;
        const int kc = pc << 5;
#pragma unroll
        for (int rr = 0; rr < 2; rr++) {
            int row = ln + (rr << 6);
            const char* src = (const char*)(gsrc + (size_t)(rbase + row) * Kdim + kc);
            uint32_t dst = dstT + (uint32_t)row * 80u;
#pragma unroll
            for (int cc = 0; cc < 4; cc++)
                CP_ASYNC16(dst + cc * 16, src + cc * 16);
        }
        CP_COMMIT();
    }

    const int warp_m = wid & 3;
    const int warp_n = wid >> 2;

    float acc[2][8][4];
#pragma unroll
    for (int mf = 0; mf < 2; mf++)
#pragma unroll
        for (int j = 0; j < 8; j++)
#pragma unroll
            for (int q = 0; q < 4; q++) acc[mf][j][q] = 0.f;

    for (int c = 0; c < NC; c++) {
        if (c + 2 < NC) {
            const int kc = (c + 2) << 5;
            const uint32_t dstT = sbase + (uint32_t)((c + 2) % NSTAGE) * BUF_B
                                        + (uint32_t)t * TILE_B;
#pragma unroll
            for (int rr = 0; rr < 2; rr++) {
                int row = ln + (rr << 6);
                const char* src = (const char*)(gsrc + (size_t)(rbase + row) * Kdim + kc);
                uint32_t dst = dstT + (uint32_t)row * 80u;
#pragma unroll
                for (int cc = 0; cc < 4; cc++)
                    CP_ASYNC16(dst + cc * 16, src + cc * 16);
            }
            CP_COMMIT();
            CP_WAIT2();
        } else if (c + 1 < NC) {
            CP_WAIT1();
        } else {
            CP_WAIT0();
        }
        __syncthreads();

        const uint32_t buf = sbase + (uint32_t)(c % NSTAGE) * BUF_B;
        const uint32_t sAh = buf;
        const uint32_t sAl = buf + TILE_B;
        const uint32_t sBh = buf + 2 * TILE_B;
        const uint32_t sBl = buf + 3 * TILE_B;

#pragma unroll
        for (int ks = 0; ks < 2; ks++) {
            const uint32_t kb = (uint32_t)(ks * 32);

            uint32_t a_h[2][4], a_l[2][4];
#pragma unroll
            for (int mf = 0; mf < 2; mf++) {
                uint32_t row = (uint32_t)(warp_m * 32 + mf * 16 + (lane & 15));
                uint32_t col = (uint32_t)((lane >> 4) * 16) + kb;
                LDSM_X4(a_h[mf], sAh + row * 80u + col);
                LDSM_X4(a_l[mf], sAl + row * 80u + col);
            }

            const int l8  = lane & 7;
            const int grp = lane >> 3;
            const uint32_t brow_off = (uint32_t)(l8 + ((grp & 2) ? 8 : 0));
            const uint32_t bcol     = kb + ((grp & 1) ? 16u : 0u);
#pragma unroll
            for (int g = 0; g < 4; g++) {
                uint32_t nrow = (uint32_t)(warp_n * 64 + g * 16) + brow_off;
                uint32_t b_h[4], b_l[4];
                LDSM_X4(b_h, sBh + nrow * 80u + bcol);
                LDSM_X4(b_l, sBl + nrow * 80u + bcol);
#pragma unroll
                for (int mf = 0; mf < 2; mf++) {
                    MMA16816(acc[mf][2 * g],     a_h[mf], b_h[0], b_h[1]);
                    MMA16816(acc[mf][2 * g],     a_h[mf], b_l[0], b_l[1]);
                    MMA16816(acc[mf][2 * g],     a_l[mf], b_h[0], b_h[1]);
                    MMA16816(acc[mf][2 * g + 1], a_h[mf], b_h[2], b_h[3]);
                    MMA16816(acc[mf][2 * g + 1], a_h[mf], b_l[2], b_l[3]);
                    MMA16816(acc[mf][2 * g + 1], a_l[mf], b_h[2], b_h[3]);
                }
            }
        }
        __syncthreads();
    }

#pragma unroll
    for (int mf = 0; mf < 2; mf++) {
#pragma unroll
        for (int j = 0; j < 8; j++) {
            int r0 = rowC + warp_m * 32 + mf * 16 + (lane >> 2);
            int cc = colC + warp_n * 64 + j * 8 + (lane & 3) * 2;
            *(float2*)(C + (size_t)r0 * ldc + cc)       = make_float2(acc[mf][j][0], acc[mf][j][1]);
            *(float2*)(C + (size_t)(r0 + 8) * ldc + cc) = make_float2(acc[mf][j][2], acc[mf][j][3]);
        }
    }
}

__global__ __launch_bounds__(256)
void gemm_qkv(const __nv_bfloat16* __restrict__ xh, const __nv_bfloat16* __restrict__ xl,
              const __nv_bfloat16* __restrict__ wqh, const __nv_bfloat16* __restrict__ wql,
              const __nv_bfloat16* __restrict__ wkh, const __nv_bfloat16* __restrict__ wkl,
              const __nv_bfloat16* __restrict__ wvh, const __nv_bfloat16* __restrict__ wvl,
              float* __restrict__ Qo, float* __restrict__ Ko, float* __restrict__ Vo)
{
    extern __shared__ char sm[];
    int bx = blockIdx.x;
    const __nv_bfloat16 *Bh, *Bl; float* C; int ldc, colC;
    if (bx < 16)      { Bh = wqh; Bl = wql; C = Qo; ldc = 2048; colC = bx * 128; }
    else if (bx < 20) { Bh = wkh; Bl = wkl; C = Ko; ldc = 512;  colC = (bx - 16) * 128; }
    else              { Bh = wvh; Bl = wvl; C = Vo; ldc = 512;  colC = (bx - 20) * 128; }
    gemm_body(xh, xl, Bh, Bl, C, 2048, ldc, blockIdx.y * 128, colC, sm);
}

__global__ __launch_bounds__(256)
void gemm_mma(const __nv_bfloat16* __restrict__ Ah, const __nv_bfloat16* __restrict__ Al,
              const __nv_bfloat16* __restrict__ Bh, const __nv_bfloat16* __restrict__ Bl,
              float* __restrict__ C, int Kdim, int ldc)
{
    extern __shared__ char sm[];
    gemm_body(Ah, Al, Bh, Bl, C, Kdim, ldc, blockIdx.y * 128, blockIdx.x * 128, sm);
}

// ================= RoPE -> bf16 hi/lo, head-major =================
// Q: scale folded. out layout [b][h][t][128]
__global__ __launch_bounds__(256) void rope_q_bf(const float* __restrict__ Q,
                                                 const int* __restrict__ positions,
                                                 __nv_bfloat16* __restrict__ oh,
                                                 __nv_bfloat16* __restrict__ ol)
{
    int idx = blockIdx.x * 256 + threadIdx.x;
    int j = idx & 63;
    int t = (idx >> 6) & 2047;
    int h = (idx >> 17) & 15;
    int b = idx >> 21;
    float pos = (float)positions[b * 2048 + t];
    float inv_freq = powf(10000.0f, -(float)j * (1.0f / 64.0f));
    float ang = pos * inv_freq;
    float s, c;
    sincosf(ang, &s, &c);
    const float* p = Q + ((size_t)(b * 2048 + t)) * 2048 + h * 128;
    float x1 = p[j], x2 = p[j + 64];
    const float scale = 0.08838834764831845f;
    float y1 = (x1 * c - x2 * s) * scale;
    float y2 = (x1 * s + x2 * c) * scale;
    size_t ob = ((size_t)((b * 16 + h) * 2048 + t)) * 128;
    __nv_bfloat16 h1 = __float2bfloat16(y1);
    __nv_bfloat16 h2 = __float2bfloat16(y2);
    oh[ob + j]      = h1;
    oh[ob + j + 64] = h2;
    ol[ob + j]      = __float2bfloat16(y1 - __bfloat162float(h1));
    ol[ob + j + 64] = __float2bfloat16(y2 - __bfloat162float(h2));
}

__global__ __launch_bounds__(256) void rope_k_bf(const float* __restrict__ K,
                                                 const int* __restrict__ positions,
                                                 __nv_bfloat16* __restrict__ oh,
                                                 __nv_bfloat16* __restrict__ ol)
{
    int idx = blockIdx.x * 256 + threadIdx.x;
    int j = idx & 63;
    int t = (idx >> 6) & 2047;
    int h = (idx >> 17) & 3;
    int b = idx >> 19;
    float pos = (float)positions[b * 2048 + t];
    float inv_freq = powf(10000.0f, -(float)j * (1.0f / 64.0f));
    float ang = pos * inv_freq;
    float s, c;
    sincosf(ang, &s, &c);
    const float* p = K + ((size_t)(b * 2048 + t)) * 512 + h * 128;
    float x1 = p[j], x2 = p[j + 64];
    float y1 = x1 * c - x2 * s;
    float y2 = x1 * s + x2 * c;
    size_t ob = ((size_t)((b * 4 + h) * 2048 + t)) * 128;
    __nv_bfloat16 h1 = __float2bfloat16(y1);
    __nv_bfloat16 h2 = __float2bfloat16(y2);
    oh[ob + j]      = h1;
    oh[ob + j + 64] = h2;
    ol[ob + j]      = __float2bfloat16(y1 - __bfloat162float(h1));
    ol[ob + j + 64] = __float2bfloat16(y2 - __bfloat162float(h2));
}

// ================= V transpose -> bf16 hi/lo  [b][kvh][d][t] =================
__global__ __launch_bounds__(256) void prep_v(const float* __restrict__ V,
                                              __nv_bfloat16* __restrict__ vh,
                                              __nv_bfloat16* __restrict__ vl)
{
    __shared__ float tile[64][129];
    int tt = blockIdx.x, kvh = blockIdx.y, b = blockIdx.z;
    int tid = threadIdx.x, wid = tid >> 5, lane = tid & 31;

    for (int i = tid; i < 64 * 32; i += 256) {
        int r = i >> 5, c4 = (i & 31) << 2;
        float4 v = *(const float4*)(V + ((size_t)(b * 2048 + tt * 64 + r)) * 512 + kvh * 128 + c4);
        tile[r][c4 + 0] = v.x; tile[r][c4 + 1] = v.y;
        tile[r][c4 + 2] = v.z; tile[r][c4 + 3] = v.w;
    }
    __syncthreads();

#pragma unroll
    for (int pass = 0; pass < 4; pass++) {
        int d = pass * 32 + wid * 4 + (lane >> 3);
        int t0 = (lane & 7) * 8;
        size_t ob = ((size_t)((b * 4 + kvh) * 128 + d)) * 2048 + tt * 64 + t0;
        uint32_t hh[4], ll[4];
#pragma unroll
        for (int u = 0; u < 4; u++) {
            float x0 = tile[t0 + 2 * u][d];
            float x1 = tile[t0 + 2 * u + 1][d];
            __nv_bfloat16 a0 = __float2bfloat16(x0);
            __nv_bfloat16 a1 = __float2bfloat16(x1);
            __nv_bfloat162 hp(a0, a1);
            __nv_bfloat162 lp(__float2bfloat16(x0 - __bfloat162float(a0)),
                              __float2bfloat16(x1 - __bfloat162float(a1)));
            hh[u] = *(uint32_t*)&hp;
            ll[u] = *(uint32_t*)&lp;
        }
        *(uint4*)(vh + ob) = make_uint4(hh[0], hh[1], hh[2], hh[3]);
        *(uint4*)(vl + ob) = make_uint4(ll[0], ll[1], ll[2], ll[3]);
    }
}

// ================= flash attention on tensor cores =================
// CTA: 128 q-rows x head x batch. KV tile = 64, double-buffered cp.async.
#define FK_ROW 272u                    // 256B row + 16B pad (Q and K tiles)
#define FV_ROW 144u                    // 128B row + 16B pad (Vt tiles)
#define QTILE_B (128u * FK_ROW)        // 34816
#define KTILE_B (64u * FK_ROW)         // 17408
#define VTILE_B (128u * FV_ROW)        // 18432
#define STAGE_B (2u * KTILE_B + 2u * VTILE_B)   // 71680
#define FA2_SMEM (2u * QTILE_B + 2u * STAGE_B)  // 212992

__global__ __launch_bounds__(256)
void flash_mma(const __nv_bfloat16* __restrict__ Qh, const __nv_bfloat16* __restrict__ Ql,
               const __nv_bfloat16* __restrict__ Kh, const __nv_bfloat16* __restrict__ Kl,
               const __nv_bfloat16* __restrict__ Vh, const __nv_bfloat16* __restrict__ Vl,
               float* __restrict__ ctx)
{
    extern __shared__ char sm[];
    const uint32_t sb = smem_u32(sm);
    const int qt = 15 - blockIdx.x;          // heavy tiles first
    const int h = blockIdx.y, b = blockIdx.z;
    const int kvh = h >> 2;
    const int tid = threadIdx.x, wid = tid >> 5, lane = tid & 31;

    const uint32_t sQh = sb, sQl = sb + QTILE_B;
    const uint32_t stg0 = sb + 2u * QTILE_B;
    const int nkt = 2 * qt + 2;

    const __nv_bfloat16* gQh = Qh + ((size_t)((b * 16 + h) * 2048 + qt * 128)) * 128;
    const __nv_bfloat16* gQl = Ql + ((size_t)((b * 16 + h) * 2048 + qt * 128)) * 128;
    const __nv_bfloat16* gKh = Kh + ((size_t)((b * 4 + kvh) * 2048)) * 128;
    const __nv_bfloat16* gKl = Kl + ((size_t)((b * 4 + kvh) * 2048)) * 128;
    const __nv_bfloat16* gVh = Vh + ((size_t)((b * 4 + kvh) * 128)) * 2048;
    const __nv_bfloat16* gVl = Vl + ((size_t)((b * 4 + kvh) * 128)) * 2048;

    auto load_stage = [&](int kt, int s) {
        const uint32_t base = stg0 + (uint32_t)s * STAGE_B;
        {   // K tiles: 64 rows x 256B, hi+lo
            int row = tid >> 2, q4 = tid & 3;
            const char* sh = (const char*)(gKh + ((size_t)(kt * 64 + row)) * 128) + q4 * 64;
            const char* sl = (const char*)(gKl + ((size_t)(kt * 64 + row)) * 128) + q4 * 64;
            uint32_t dh = base + (uint32_t)row * FK_ROW + q4 * 64;
            uint32_t dl = dh + KTILE_B;
#pragma unroll
            for (int i = 0; i < 4; i++) {
                CP_ASYNC16(dh + i * 16, sh + i * 16);
                CP_ASYNC16(dl + i * 16, sl + i * 16);
            }
        }
        {   // V tiles: 128 rows x 128B, hi+lo
            int row = tid >> 1, hf = tid & 1;
            const char* sh = (const char*)(gVh + (size_t)row * 2048 + kt * 64) + hf * 64;
            const char* sl = (const char*)(gVl + (size_t)row * 2048 + kt * 64) + hf * 64;
            uint32_t dh = base + 2u * KTILE_B + (uint32_t)row * FV_ROW + hf * 64;
            uint32_t dl = dh + VTILE_B;
#pragma unroll
            for (int i = 0; i < 4; i++) {
                CP_ASYNC16(dh + i * 16, sh + i * 16);
                CP_ASYNC16(dl + i * 16, sl + i * 16);
            }
        }
    };

    // prologue: Q + stage0 as group0, stage1 as group1
    {
        int row = tid >> 1, part = tid & 1;
        const char* s0 = (const char*)(gQh + (size_t)row * 128) + part * 128;
        const char* s1 = (const char*)(gQl + (size_t)row * 128) + part * 128;
        uint32_t d0 = sQh + (uint32_t)row * FK_ROW + part * 128;
        uint32_t d1 = sQl + (uint32_t)row * FK_ROW + part * 128;
#pragma unroll
        for (int i = 0; i < 8; i++) {
            CP_ASYNC16(d0 + i * 16, s0 + i * 16);
            CP_ASYNC16(d1 + i * 16, s1 + i * 16);
        }
    }
    load_stage(0, 0);
    CP_COMMIT();
    load_stage(1, 1);
    CP_COMMIT();

    // per-thread state: 2 rows (r0, r0+8) within warp's m16
    float m0 = -INFINITY, m1 = -INFINITY, l0 = 0.f, l1 = 0.f;
    float oacc[16][4];
#pragma unroll
    for (int f = 0; f < 16; f++)
#pragma unroll
        for (int q = 0; q < 4; q++) oacc[f][q] = 0.f;

    const int l8  = lane & 7;
    const int grp = lane >> 3;
    const uint32_t brow = (uint32_t)(l8 + ((grp & 2) ? 8 : 0));
    const uint32_t bksel = (grp & 1) ? 16u : 0u;

    for (int kt = 0; kt < nkt; kt++) {
        if (kt < nkt - 1) { CP_WAIT1(); } else { CP_WAIT0(); }
        __syncthreads();

        const uint32_t stK = stg0 + (uint32_t)(kt & 1) * STAGE_B;
        const uint32_t stKh = stK, stKl = stK + KTILE_B;
        const uint32_t stVh = stK + 2u * KTILE_B, stVl = stVh + VTILE_B;

        // ---- S = Q K^T : warp m16 x n64, k = 128 ----
        float s[8][4];
#pragma unroll
        for (int j = 0; j < 8; j++)
#pragma unroll
            for (int q = 0; q < 4; q++) s[j][q] = 0.f;

#pragma unroll
        for (int ks = 0; ks < 8; ks++) {
            uint32_t arow = (uint32_t)(wid * 16 + (lane & 15));
            uint32_t acol = (uint32_t)(ks * 32 + (lane >> 4) * 16);
            uint32_t aqh[4], aql[4];
            LDSM_X4(aqh, sQh + arow * FK_ROW + acol);
            LDSM_X4(aql, sQl + arow * FK_ROW + acol);

            uint32_t bcol = (uint32_t)(ks * 32) + bksel;
#pragma unroll
            for (int g = 0; g < 4; g++) {
                uint32_t nrow = (uint32_t)(g * 16) + brow;
                uint32_t bh[4], bl[4];
                LDSM_X4(bh, stKh + nrow * FK_ROW + bcol);
                LDSM_X4(bl, stKl + nrow * FK_ROW + bcol);
                MMA16816(s[2 * g],     aqh, bh[0], bh[1]);
                MMA16816(s[2 * g],     aqh, bl[0], bl[1]);
                MMA16816(s[2 * g],     aql, bh[0], bh[1]);
                MMA16816(s[2 * g + 1], aqh, bh[2], bh[3]);
                MMA16816(s[2 * g + 1], aqh, bl[2], bl[3]);
                MMA16816(s[2 * g + 1], aql, bh[2], bh[3]);
            }
        }

        // ---- causal mask (diagonal tiles only) ----
        if (kt >= 2 * qt) {
            int grow0 = qt * 128 + wid * 16 + (lane >> 2);
            int gc0 = kt * 64 + (lane & 3) * 2;
#pragma unroll
            for (int j = 0; j < 8; j++) {
                int c = gc0 + j * 8;
                if (c     > grow0)     s[j][0] = -1e9f;
                if (c + 1 > grow0)     s[j][1] = -1e9f;
                if (c     > grow0 + 8) s[j][2] = -1e9f;
                if (c + 1 > grow0 + 8) s[j][3] = -1e9f;
            }
        }

        // ---- online softmax (rows r0, r0+8) ----
        float mt0 = -INFINITY, mt1 = -INFINITY;
#pragma unroll
        for (int j = 0; j < 8; j++) {
            mt0 = fmaxf(mt0, fmaxf(s[j][0], s[j][1]));
            mt1 = fmaxf(mt1, fmaxf(s[j][2], s[j][3]));
        }
        mt0 = fmaxf(mt0, __shfl_xor_sync(0xffffffffu, mt0, 1));
        mt0 = fmaxf(mt0, __shfl_xor_sync(0xffffffffu, mt0, 2));
        mt1 = fmaxf(mt1, __shfl_xor_sync(0xffffffffu, mt1, 1));
        mt1 = fmaxf(mt1, __shfl_xor_sync(0xffffffffu, mt1, 2));

        float mn0 = fmaxf(m0, mt0), mn1 = fmaxf(m1, mt1);
        float corr0 = __expf(m0 - mn0), corr1 = __expf(m1 - mn1);
        m0 = mn0; m1 = mn1;

        float rs0 = 0.f, rs1 = 0.f;
#pragma unroll
        for (int j = 0; j < 8; j++) {
            s[j][0] = __expf(s[j][0] - mn0);
            s[j][1] = __expf(s[j][1] - mn0);
            s[j][2] = __expf(s[j][2] - mn1);
            s[j][3] = __expf(s[j][3] - mn1);
            rs0 += s[j][0] + s[j][1];
            rs1 += s[j][2] + s[j][3];
        }
        rs0 += __shfl_xor_sync(0xffffffffu, rs0, 1);
        rs0 += __shfl_xor_sync(0xffffffffu, rs0, 2);
        rs1 += __shfl_xor_sync(0xffffffffu, rs1, 1);
        rs1 += __shfl_xor_sync(0xffffffffu, rs1, 2);
        l0 = l0 * corr0 + rs0;
        l1 = l1 * corr1 + rs1;

#pragma unroll
        for (int f = 0; f < 16; f++) {
            oacc[f][0] *= corr0; oacc[f][1] *= corr0;
            oacc[f][2] *= corr1; oacc[f][3] *= corr1;
        }

        // ---- O += P V : P from registers (C-frag == A-frag layout) ----
#pragma unroll
        for (int g = 0; g < 4; g++) {
            const int f0 = 2 * g, f1 = 2 * g + 1;
            uint32_t pah[4], pal[4];
            pah[0] = pack_bf2(s[f0][0], s[f0][1]);
            pah[1] = pack_bf2(s[f0][2], s[f0][3]);
            pah[2] = pack_bf2(s[f1][0], s[f1][1]);
            pah[3] = pack_bf2(s[f1][2], s[f1][3]);
            pal[0] = pack_bf2(s[f0][0] - bf_round(s[f0][0]), s[f0][1] - bf_round(s[f0][1]));
            pal[1] = pack_bf2(s[f0][2] - bf_round(s[f0][2]), s[f0][3] - bf_round(s[f0][3]));
            pal[2] = pack_bf2(s[f1][0] - bf_round(s[f1][0]), s[f1][1] - bf_round(s[f1][1]));
            pal[3] = pack_bf2(s[f1][2] - bf_round(s[f1][2]), s[f1][3] - bf_round(s[f1][3]));

            uint32_t bco = (uint32_t)(g * 32) + bksel;
#pragma unroll
            for (int nb = 0; nb < 8; nb++) {
                uint32_t nrow = (uint32_t)(nb * 16) + brow;
                uint32_t vhf[4], vlf[4];
                LDSM_X4(vhf, stVh + nrow * FV_ROW + bco);
                LDSM_X4(vlf, stVl + nrow * FV_ROW + bco);
                MMA16816(oacc[2 * nb],     pah, vhf[0], vhf[1]);
                MMA16816(oacc[2 * nb],     pah, vlf[0], vlf[1]);
                MMA16816(oacc[2 * nb],     pal, vhf[0], vhf[1]);
                MMA16816(oacc[2 * nb + 1], pah, vhf[2], vhf[3]);
                MMA16816(oacc[2 * nb + 1], pah, vlf[2], vlf[3]);
                MMA16816(oacc[2 * nb + 1], pal, vhf[2], vhf[3]);
            }
        }

        __syncthreads();
        if (kt + 2 < nkt) {
            load_stage(kt + 2, kt & 1);
            CP_COMMIT();
        }
    }

    // ---- epilogue: ctx[b, t, h*128 + d] = O / l ----
    float inv0 = 1.0f / l0, inv1 = 1.0f / l1;
    int trow = qt * 128 + wid * 16 + (lane >> 2);
    int c2 = (lane & 3) * 2;
    float* base0 = ctx + ((size_t)(b * 2048 + trow)) * 2048 + h * 128;
    float* base1 = base0 + (size_t)8 * 2048;
#pragma unroll
    for (int f = 0; f < 16; f++) {
        int col = f * 8 + c2;
        *(float2*)(base0 + col) = make_float2(oacc[f][0] * inv0, oacc[f][1] * inv0);
        *(float2*)(base1 + col) = make_float2(oacc[f][2] * inv1, oacc[f][3] * inv1);
    }
}

// ================= launch =================
extern "C" void kernel_launch(void* const* d_in, const int* in_sizes, int n_in,
                              void* d_out, int out_size)
{
    const float* x   = (const float*)d_in[0];
    const int*   pos = (const int*)d_in[1];
    const float* wq  = (const float*)d_in[2];
    const float* wk  = (const float*)d_in[3];
    const float* wv  = (const float*)d_in[4];
    const float* wo  = (const float*)d_in[5];
    float* out = (float*)d_out;

    float *Qp, *Kp, *Vp, *Cp;
    cudaGetSymbolAddress((void**)&Qp, g_Q);
    cudaGetSymbolAddress((void**)&Kp, g_K);
    cudaGetSymbolAddress((void**)&Vp, g_V);
    cudaGetSymbolAddress((void**)&Cp, g_ctx);

    __nv_bfloat16 *xh, *xl, *wqh, *wql, *wkh, *wkl, *wvh, *wvl, *woh, *wol, *ch, *cl;
    cudaGetSymbolAddress((void**)&xh,  g_xh);  cudaGetSymbolAddress((void**)&xl,  g_xl);
    cudaGetSymbolAddress((void**)&wqh, g_wqh); cudaGetSymbolAddress((void**)&wql, g_wql);
    cudaGetSymbolAddress((void**)&wkh, g_wkh); cudaGetSymbolAddress((void**)&wkl, g_wkl);
    cudaGetSymbolAddress((void**)&wvh, g_wvh); cudaGetSymbolAddress((void**)&wvl, g_wvl);
    cudaGetSymbolAddress((void**)&woh, g_woh); cudaGetSymbolAddress((void**)&wol, g_wol);
    cudaGetSymbolAddress((void**)&ch,  g_ch);  cudaGetSymbolAddress((void**)&cl,  g_cl);

    __nv_bfloat16 *qbh, *qbl, *kbh, *kbl, *vth, *vtl;
    cudaGetSymbolAddress((void**)&qbh, g_qbh); cudaGetSymbolAddress((void**)&qbl, g_qbl);
    cudaGetSymbolAddress((void**)&kbh, g_kbh); cudaGetSymbolAddress((void**)&kbl, g_kbl);
    cudaGetSymbolAddress((void**)&vth, g_vth); cudaGetSymbolAddress((void**)&vtl, g_vtl);

    cudaFuncSetAttribute(gemm_qkv, cudaFuncAttributeMaxDynamicSharedMemorySize, GEMM_SMEM);
    cudaFuncSetAttribute(gemm_mma, cudaFuncAttributeMaxDynamicSharedMemorySize, GEMM_SMEM);
    cudaFuncSetAttribute(flash_mma, cudaFuncAttributeMaxDynamicSharedMemorySize, FA2_SMEM);

    // bf16 hi/lo splits
    split_bf16<<<(4096 * 2048 / 4) / 256, 256>>>(x,  xh,  xl,  4096 * 2048 / 4);
    split_bf16<<<(2048 * 2048 / 4) / 256, 256>>>(wq, wqh, wql, 2048 * 2048 / 4);
    split_bf16<<<(512  * 2048 / 4) / 256, 256>>>(wk, wkh, wkl, 512 * 2048 / 4);
    split_bf16<<<(512  * 2048 / 4) / 256, 256>>>(wv, wvh, wvl, 512 * 2048 / 4);
    split_bf16<<<(2048 * 2048 / 4) / 256, 256>>>(wo, woh, wol, 2048 * 2048 / 4);

    // fused QKV projection (tensor cores)
    gemm_qkv<<<dim3(24, 32), 256, GEMM_SMEM>>>(xh, xl, wqh, wql, wkh, wkl, wvh, wvl,
                                               Qp, Kp, Vp);

    // RoPE -> bf16 hi/lo head-major (Q pre-scaled); V -> transposed bf16 hi/lo
    rope_q_bf<<<16384, 256>>>(Qp, pos, qbh, qbl);
    rope_k_bf<<<4096, 256>>>(Kp, pos, kbh, kbl);
    prep_v<<<dim3(32, 4, 2), 256>>>(Vp, vth, vtl);

    // causal GQA attention on tensor cores
    flash_mma<<<dim3(16, 16, 2), 256, FA2_SMEM>>>(qbh, qbl, kbh, kbl, vth, vtl, Cp);

    // O projection (tensor cores)
    split_bf16<<<(4096 * 2048 / 4) / 256, 256>>>(Cp, ch, cl, 4096 * 2048 / 4);
    gemm_mma<<<dim3(16, 32), 256, GEMM_SMEM>>>(ch, cl, woh, wol, out, 2048, 2048);
}

// round 12
// speedup vs baseline: 2.2488x; 1.0175x over previous
#include <cuda_runtime.h>
#include <cuda_bf16.h>
#include <math.h>
#include <cstdint>

// ================= helpers =================
__device__ __forceinline__ uint32_t smem_u32(const void* p) {
    uint32_t a;
    asm("{ .reg .u64 t; cvta.to.shared.u64 t, %1; cvt.u32.u64 %0, t; }" : "=r"(a) : "l"(p));
    return a;
}

#define CP_ASYNC16(dst, src) \
    asm volatile("cp.async.cg.shared.global [%0], [%1], 16;" :: "r"(dst), "l"(src))
#define CP_COMMIT() asm volatile("cp.async.commit_group;" ::: "memory")
#define CP_WAIT2()  asm volatile("cp.async.wait_group 2;" ::: "memory")
#define CP_WAIT1()  asm volatile("cp.async.wait_group 1;" ::: "memory")
#define CP_WAIT0()  asm volatile("cp.async.wait_group 0;" ::: "memory")

#define LDSM_X4(r, addr) \
    asm volatile("ldmatrix.sync.aligned.m8n8.x4.shared.b16 {%0,%1,%2,%3}, [%4];" \
        : "=r"((r)[0]), "=r"((r)[1]), "=r"((r)[2]), "=r"((r)[3]) : "r"(addr))
#define MMA16816(d, a, b0, b1) \
    asm volatile("mma.sync.aligned.m16n8k16.row.col.f32.bf16.bf16.f32 " \
        "{%0,%1,%2,%3}, {%4,%5,%6,%7}, {%8,%9}, {%0,%1,%2,%3};" \
        : "+f"((d)[0]), "+f"((d)[1]), "+f"((d)[2]), "+f"((d)[3]) \
        : "r"((a)[0]), "r"((a)[1]), "r"((a)[2]), "r"((a)[3]), "r"(b0), "r"(b1))

__device__ __forceinline__ uint32_t pack_bf2(float lo, float hi) {
    uint32_t r;
    asm("cvt.rn.bf16x2.f32 %0, %1, %2;" : "=r"(r) : "f"(hi), "f"(lo));
    return r;
}
__device__ __forceinline__ float bf_round(float x) {
    return __bfloat162float(__float2bfloat16(x));
}

// ================= scratch (no allocations allowed) =================
__device__ float g_Q[4096 * 2048];
__device__ float g_K[4096 * 512];
__device__ float g_V[4096 * 512];

__device__ __nv_bfloat16 g_xh[4096 * 2048];
__device__ __nv_bfloat16 g_xl[4096 * 2048];
__device__ __nv_bfloat16 g_wqh[2048 * 2048];
__device__ __nv_bfloat16 g_wql[2048 * 2048];
__device__ __nv_bfloat16 g_wkh[512 * 2048];
__device__ __nv_bfloat16 g_wkl[512 * 2048];
__device__ __nv_bfloat16 g_wvh[512 * 2048];
__device__ __nv_bfloat16 g_wvl[512 * 2048];
__device__ __nv_bfloat16 g_woh[2048 * 2048];
__device__ __nv_bfloat16 g_wol[2048 * 2048];
__device__ __nv_bfloat16 g_ch[4096 * 2048];
__device__ __nv_bfloat16 g_cl[4096 * 2048];

// attention operands (head-major)
__device__ __nv_bfloat16 g_qbh[2 * 16 * 2048 * 128];
__device__ __nv_bfloat16 g_qbl[2 * 16 * 2048 * 128];
__device__ __nv_bfloat16 g_kbh[2 * 4 * 2048 * 128];
__device__ __nv_bfloat16 g_kbl[2 * 4 * 2048 * 128];
__device__ __nv_bfloat16 g_vth[2 * 4 * 128 * 2048];   // V transposed [b][kvh][d][t]
__device__ __nv_bfloat16 g_vtl[2 * 4 * 128 * 2048];

// ================= fp32 -> bf16 hi/lo split =================
__global__ __launch_bounds__(256) void split_bf16(const float* __restrict__ in,
                                                  __nv_bfloat16* __restrict__ hi,
                                                  __nv_bfloat16* __restrict__ lo,
                                                  int n4)
{
    int i = blockIdx.x * 256 + threadIdx.x;
    if (i >= n4) return;
    float4 v = ((const float4*)in)[i];
    __nv_bfloat16 h0 = __float2bfloat16(v.x);
    __nv_bfloat16 h1 = __float2bfloat16(v.y);
    __nv_bfloat16 h2 = __float2bfloat16(v.z);
    __nv_bfloat16 h3 = __float2bfloat16(v.w);
    __nv_bfloat16 l0 = __float2bfloat16(v.x - __bfloat162float(h0));
    __nv_bfloat16 l1 = __float2bfloat16(v.y - __bfloat162float(h1));
    __nv_bfloat16 l2 = __float2bfloat16(v.z - __bfloat162float(h2));
    __nv_bfloat16 l3 = __float2bfloat16(v.w - __bfloat162float(h3));
    ((__nv_bfloat162*)hi)[2 * i]     = __nv_bfloat162(h0, h1);
    ((__nv_bfloat162*)hi)[2 * i + 1] = __nv_bfloat162(h2, h3);
    ((__nv_bfloat162*)lo)[2 * i]     = __nv_bfloat162(l0, l1);
    ((__nv_bfloat162*)lo)[2 * i + 1] = __nv_bfloat162(l2, l3);
}

// ================= mma.sync split-bf16 GEMM core =================
// CTA 128x128, 8 warps (4 x 2), warp tile 32x64. K-chunk 32, 3-stage cp.async.
// MMA issue order: pass-outer round-robin over 4 accumulators (hides HMMA RAW latency).
#define TILE_B  (128 * 80)
#define BUF_B   (4 * TILE_B)
#define NSTAGE  3
#define GEMM_SMEM (NSTAGE * BUF_B)

__device__ __forceinline__ void gemm_body(
    const __nv_bfloat16* __restrict__ Ah, const __nv_bfloat16* __restrict__ Al,
    const __nv_bfloat16* __restrict__ Bh, const __nv_bfloat16* __restrict__ Bl,
    float* __restrict__ C, int Kdim, int ldc, int rowC, int colC, char* smptr)
{
    const uint32_t sbase = smem_u32(smptr);
    const int tid  = threadIdx.x;
    const int wid  = tid >> 5;
    const int lane = tid & 31;

    const int t  = tid >> 6;
    const int ln = tid & 63;
    const __nv_bfloat16* gsrc = (t == 0) ? Ah : (t == 1) ? Al : (t == 2) ? Bh : Bl;
    const int rbase = (t < 2) ? rowC : colC;

    const int NC = Kdim >> 5;

#pragma unroll
    for (int pc = 0; pc < 2; pc++) {
        const uint32_t dstT = sbase + (uint32_t)pc * BUF_B + (uint32_t)t * TILE_B;
        const int kc = pc << 5;
#pragma unroll
        for (int rr = 0; rr < 2; rr++) {
            int row = ln + (rr << 6);
            const char* src = (const char*)(gsrc + (size_t)(rbase + row) * Kdim + kc);
            uint32_t dst = dstT + (uint32_t)row * 80u;
#pragma unroll
            for (int cc = 0; cc < 4; cc++)
                CP_ASYNC16(dst + cc * 16, src + cc * 16);
        }
        CP_COMMIT();
    }

    const int warp_m = wid & 3;
    const int warp_n = wid >> 2;

    float acc[2][8][4];
#pragma unroll
    for (int mf = 0; mf < 2; mf++)
#pragma unroll
        for (int j = 0; j < 8; j++)
#pragma unroll
            for (int q = 0; q < 4; q++) acc[mf][j][q] = 0.f;

    const int l8  = lane & 7;
    const int grp = lane >> 3;
    const uint32_t brow_off = (uint32_t)(l8 + ((grp & 2) ? 8 : 0));
    const uint32_t bsel     = (grp & 1) ? 16u : 0u;

    for (int c = 0; c < NC; c++) {
        if (c + 2 < NC) {
            const int kc = (c + 2) << 5;
            const uint32_t dstT = sbase + (uint32_t)((c + 2) % NSTAGE) * BUF_B
                                        + (uint32_t)t * TILE_B;
#pragma unroll
            for (int rr = 0; rr < 2; rr++) {
                int row = ln + (rr << 6);
                const char* src = (const char*)(gsrc + (size_t)(rbase + row) * Kdim + kc);
                uint32_t dst = dstT + (uint32_t)row * 80u;
#pragma unroll
                for (int cc = 0; cc < 4; cc++)
                    CP_ASYNC16(dst + cc * 16, src + cc * 16);
            }
            CP_COMMIT();
            CP_WAIT2();
        } else if (c + 1 < NC) {
            CP_WAIT1();
        } else {
            CP_WAIT0();
        }
        __syncthreads();

        const uint32_t buf = sbase + (uint32_t)(c % NSTAGE) * BUF_B;
        const uint32_t sAh = buf;
        const uint32_t sAl = buf + TILE_B;
        const uint32_t sBh = buf + 2 * TILE_B;
        const uint32_t sBl = buf + 3 * TILE_B;

#pragma unroll
        for (int ks = 0; ks < 2; ks++) {
            const uint32_t kb = (uint32_t)(ks * 32);

            uint32_t a_h[2][4], a_l[2][4];
#pragma unroll
            for (int mf = 0; mf < 2; mf++) {
                uint32_t row = (uint32_t)(warp_m * 32 + mf * 16 + (lane & 15));
                uint32_t col = (uint32_t)((lane >> 4) * 16) + kb;
                LDSM_X4(a_h[mf], sAh + row * 80u + col);
                LDSM_X4(a_l[mf], sAl + row * 80u + col);
            }

            const uint32_t bcol = kb + bsel;
#pragma unroll
            for (int g = 0; g < 4; g += 2) {
                uint32_t nrow0 = (uint32_t)(warp_n * 64 + g * 16) + brow_off;
                uint32_t nrow1 = nrow0 + 16;
                uint32_t bh0[4], bl0[4], bh1[4], bl1[4];
                LDSM_X4(bh0, sBh + nrow0 * 80u + bcol);
                LDSM_X4(bl0, sBl + nrow0 * 80u + bcol);
                LDSM_X4(bh1, sBh + nrow1 * 80u + bcol);
                LDSM_X4(bl1, sBl + nrow1 * 80u + bcol);

                // pass hh (8 MMAs, round-robin over 8 accs)
                MMA16816(acc[0][2 * g],     a_h[0], bh0[0], bh0[1]);
                MMA16816(acc[0][2 * g + 1], a_h[0], bh0[2], bh0[3]);
                MMA16816(acc[0][2 * g + 2], a_h[0], bh1[0], bh1[1]);
                MMA16816(acc[0][2 * g + 3], a_h[0], bh1[2], bh1[3]);
                MMA16816(acc[1][2 * g],     a_h[1], bh0[0], bh0[1]);
                MMA16816(acc[1][2 * g + 1], a_h[1], bh0[2], bh0[3]);
                MMA16816(acc[1][2 * g + 2], a_h[1], bh1[0], bh1[1]);
                MMA16816(acc[1][2 * g + 3], a_h[1], bh1[2], bh1[3]);
                // pass hl
                MMA16816(acc[0][2 * g],     a_h[0], bl0[0], bl0[1]);
                MMA16816(acc[0][2 * g + 1], a_h[0], bl0[2], bl0[3]);
                MMA16816(acc[0][2 * g + 2], a_h[0], bl1[0], bl1[1]);
                MMA16816(acc[0][2 * g + 3], a_h[0], bl1[2], bl1[3]);
                MMA16816(acc[1][2 * g],     a_h[1], bl0[0], bl0[1]);
                MMA16816(acc[1][2 * g + 1], a_h[1], bl0[2], bl0[3]);
                MMA16816(acc[1][2 * g + 2], a_h[1], bl1[0], bl1[1]);
                MMA16816(acc[1][2 * g + 3], a_h[1], bl1[2], bl1[3]);
                // pass lh
                MMA16816(acc[0][2 * g],     a_l[0], bh0[0], bh0[1]);
                MMA16816(acc[0][2 * g + 1], a_l[0], bh0[2], bh0[3]);
                MMA16816(acc[0][2 * g + 2], a_l[0], bh1[0], bh1[1]);
                MMA16816(acc[0][2 * g + 3], a_l[0], bh1[2], bh1[3]);
                MMA16816(acc[1][2 * g],     a_l[1], bh0[0], bh0[1]);
                MMA16816(acc[1][2 * g + 1], a_l[1], bh0[2], bh0[3]);
                MMA16816(acc[1][2 * g + 2], a_l[1], bh1[0], bh1[1]);
                MMA16816(acc[1][2 * g + 3], a_l[1], bh1[2], bh1[3]);
            }
        }
        __syncthreads();
    }

#pragma unroll
    for (int mf = 0; mf < 2; mf++) {
#pragma unroll
        for (int j = 0; j < 8; j++) {
            int r0 = rowC + warp_m * 32 + mf * 16 + (lane >> 2);
            int cc = colC + warp_n * 64 + j * 8 + (lane & 3) * 2;
            *(float2*)(C + (size_t)r0 * ldc + cc)       = make_float2(acc[mf][j][0], acc[mf][j][1]);
            *(float2*)(C + (size_t)(r0 + 8) * ldc + cc) = make_float2(acc[mf][j][2], acc[mf][j][3]);
        }
    }
}

__global__ __launch_bounds__(256)
void gemm_qkv(const __nv_bfloat16* __restrict__ xh, const __nv_bfloat16* __restrict__ xl,
              const __nv_bfloat16* __restrict__ wqh, const __nv_bfloat16* __restrict__ wql,
              const __nv_bfloat16* __restrict__ wkh, const __nv_bfloat16* __restrict__ wkl,
              const __nv_bfloat16* __restrict__ wvh, const __nv_bfloat16* __restrict__ wvl,
              float* __restrict__ Qo, float* __restrict__ Ko, float* __restrict__ Vo)
{
    extern __shared__ char sm[];
    int bx = blockIdx.x;
    const __nv_bfloat16 *Bh, *Bl; float* C; int ldc, colC;
    if (bx < 16)      { Bh = wqh; Bl = wql; C = Qo; ldc = 2048; colC = bx * 128; }
    else if (bx < 20) { Bh = wkh; Bl = wkl; C = Ko; ldc = 512;  colC = (bx - 16) * 128; }
    else              { Bh = wvh; Bl = wvl; C = Vo; ldc = 512;  colC = (bx - 20) * 128; }
    gemm_body(xh, xl, Bh, Bl, C, 2048, ldc, blockIdx.y * 128, colC, sm);
}

__global__ __launch_bounds__(256)
void gemm_mma(const __nv_bfloat16* __restrict__ Ah, const __nv_bfloat16* __restrict__ Al,
              const __nv_bfloat16* __restrict__ Bh, const __nv_bfloat16* __restrict__ Bl,
              float* __restrict__ C, int Kdim, int ldc)
{
    extern __shared__ char sm[];
    gemm_body(Ah, Al, Bh, Bl, C, Kdim, ldc, blockIdx.y * 128, blockIdx.x * 128, sm);
}

// ================= RoPE -> bf16 hi/lo, head-major =================
__global__ __launch_bounds__(256) void rope_q_bf(const float* __restrict__ Q,
                                                 const int* __restrict__ positions,
                                                 __nv_bfloat16* __restrict__ oh,
                                                 __nv_bfloat16* __restrict__ ol)
{
    int idx = blockIdx.x * 256 + threadIdx.x;
    int j = idx & 63;
    int t = (idx >> 6) & 2047;
    int h = (idx >> 17) & 15;
    int b = idx >> 21;
    float pos = (float)positions[b * 2048 + t];
    float inv_freq = powf(10000.0f, -(float)j * (1.0f / 64.0f));
    float ang = pos * inv_freq;
    float s, c;
    sincosf(ang, &s, &c);
    const float* p = Q + ((size_t)(b * 2048 + t)) * 2048 + h * 128;
    float x1 = p[j], x2 = p[j + 64];
    const float scale = 0.08838834764831845f;
    float y1 = (x1 * c - x2 * s) * scale;
    float y2 = (x1 * s + x2 * c) * scale;
    size_t ob = ((size_t)((b * 16 + h) * 2048 + t)) * 128;
    __nv_bfloat16 h1 = __float2bfloat16(y1);
    __nv_bfloat16 h2 = __float2bfloat16(y2);
    oh[ob + j]      = h1;
    oh[ob + j + 64] = h2;
    ol[ob + j]      = __float2bfloat16(y1 - __bfloat162float(h1));
    ol[ob + j + 64] = __float2bfloat16(y2 - __bfloat162float(h2));
}

__global__ __launch_bounds__(256) void rope_k_bf(const float* __restrict__ K,
                                                 const int* __restrict__ positions,
                                                 __nv_bfloat16* __restrict__ oh,
                                                 __nv_bfloat16* __restrict__ ol)
{
    int idx = blockIdx.x * 256 + threadIdx.x;
    int j = idx & 63;
    int t = (idx >> 6) & 2047;
    int h = (idx >> 17) & 3;
    int b = idx >> 19;
    float pos = (float)positions[b * 2048 + t];
    float inv_freq = powf(10000.0f, -(float)j * (1.0f / 64.0f));
    float ang = pos * inv_freq;
    float s, c;
    sincosf(ang, &s, &c);
    const float* p = K + ((size_t)(b * 2048 + t)) * 512 + h * 128;
    float x1 = p[j], x2 = p[j + 64];
    float y1 = x1 * c - x2 * s;
    float y2 = x1 * s + x2 * c;
    size_t ob = ((size_t)((b * 4 + h) * 2048 + t)) * 128;
    __nv_bfloat16 h1 = __float2bfloat16(y1);
    __nv_bfloat16 h2 = __float2bfloat16(y2);
    oh[ob + j]      = h1;
    oh[ob + j + 64] = h2;
    ol[ob + j]      = __float2bfloat16(y1 - __bfloat162float(h1));
    ol[ob + j + 64] = __float2bfloat16(y2 - __bfloat162float(h2));
}

// ================= V transpose -> bf16 hi/lo  [b][kvh][d][t] =================
__global__ __launch_bounds__(256) void prep_v(const float* __restrict__ V,
                                              __nv_bfloat16* __restrict__ vh,
                                              __nv_bfloat16* __restrict__ vl)
{
    __shared__ float tile[64][129];
    int tt = blockIdx.x, kvh = blockIdx.y, b = blockIdx.z;
    int tid = threadIdx.x, wid = tid >> 5, lane = tid & 31;

    for (int i = tid; i < 64 * 32; i += 256) {
        int r = i >> 5, c4 = (i & 31) << 2;
        float4 v = *(const float4*)(V + ((size_t)(b * 2048 + tt * 64 + r)) * 512 + kvh * 128 + c4);
        tile[r][c4 + 0] = v.x; tile[r][c4 + 1] = v.y;
        tile[r][c4 + 2] = v.z; tile[r][c4 + 3] = v.w;
    }
    __syncthreads();

#pragma unroll
    for (int pass = 0; pass < 4; pass++) {
        int d = pass * 32 + wid * 4 + (lane >> 3);
        int t0 = (lane & 7) * 8;
        size_t ob = ((size_t)((b * 4 + kvh) * 128 + d)) * 2048 + tt * 64 + t0;
        uint32_t hh[4], ll[4];
#pragma unroll
        for (int u = 0; u < 4; u++) {
            float x0 = tile[t0 + 2 * u][d];
            float x1 = tile[t0 + 2 * u + 1][d];
            __nv_bfloat16 a0 = __float2bfloat16(x0);
            __nv_bfloat16 a1 = __float2bfloat16(x1);
            __nv_bfloat162 hp(a0, a1);
            __nv_bfloat162 lp(__float2bfloat16(x0 - __bfloat162float(a0)),
                              __float2bfloat16(x1 - __bfloat162float(a1)));
            hh[u] = *(uint32_t*)&hp;
            ll[u] = *(uint32_t*)&lp;
        }
        *(uint4*)(vh + ob) = make_uint4(hh[0], hh[1], hh[2], hh[3]);
        *(uint4*)(vl + ob) = make_uint4(ll[0], ll[1], ll[2], ll[3]);
    }
}

// ================= flash attention on tensor cores =================
#define FK_ROW 272u
#define FV_ROW 144u
#define QTILE_B (128u * FK_ROW)
#define KTILE_B (64u * FK_ROW)
#define VTILE_B (128u * FV_ROW)
#define STAGE_B (2u * KTILE_B + 2u * VTILE_B)
#define FA2_SMEM (2u * QTILE_B + 2u * STAGE_B)

__global__ __launch_bounds__(256)
void flash_mma(const __nv_bfloat16* __restrict__ Qh, const __nv_bfloat16* __restrict__ Ql,
               const __nv_bfloat16* __restrict__ Kh, const __nv_bfloat16* __restrict__ Kl,
               const __nv_bfloat16* __restrict__ Vh, const __nv_bfloat16* __restrict__ Vl,
               __nv_bfloat16* __restrict__ ch, __nv_bfloat16* __restrict__ cl)
{
    extern __shared__ char sm[];
    const uint32_t sb = smem_u32(sm);
    const int qt = 15 - blockIdx.x;
    const int h = blockIdx.y, b = blockIdx.z;
    const int kvh = h >> 2;
    const int tid = threadIdx.x, wid = tid >> 5, lane = tid & 31;

    const uint32_t sQh = sb, sQl = sb + QTILE_B;
    const uint32_t stg0 = sb + 2u * QTILE_B;
    const int nkt = 2 * qt + 2;

    const __nv_bfloat16* gQh = Qh + ((size_t)((b * 16 + h) * 2048 + qt * 128)) * 128;
    const __nv_bfloat16* gQl = Ql + ((size_t)((b * 16 + h) * 2048 + qt * 128)) * 128;
    const __nv_bfloat16* gKh = Kh + ((size_t)((b * 4 + kvh) * 2048)) * 128;
    const __nv_bfloat16* gKl = Kl + ((size_t)((b * 4 + kvh) * 2048)) * 128;
    const __nv_bfloat16* gVh = Vh + ((size_t)((b * 4 + kvh) * 128)) * 2048;
    const __nv_bfloat16* gVl = Vl + ((size_t)((b * 4 + kvh) * 128)) * 2048;

    auto load_stage = [&](int kt, int s) {
        const uint32_t base = stg0 + (uint32_t)s * STAGE_B;
        {
            int row = tid >> 2, q4 = tid & 3;
            const char* sh = (const char*)(gKh + ((size_t)(kt * 64 + row)) * 128) + q4 * 64;
            const char* sl = (const char*)(gKl + ((size_t)(kt * 64 + row)) * 128) + q4 * 64;
            uint32_t dh = base + (uint32_t)row * FK_ROW + q4 * 64;
            uint32_t dl = dh + KTILE_B;
#pragma unroll
            for (int i = 0; i < 4; i++) {
                CP_ASYNC16(dh + i * 16, sh + i * 16);
                CP_ASYNC16(dl + i * 16, sl + i * 16);
            }
        }
        {
            int row = tid >> 1, hf = tid & 1;
            const char* sh = (const char*)(gVh + (size_t)row * 2048 + kt * 64) + hf * 64;
            const char* sl = (const char*)(gVl + (size_t)row * 2048 + kt * 64) + hf * 64;
            uint32_t dh = base + 2u * KTILE_B + (uint32_t)row * FV_ROW + hf * 64;
            uint32_t dl = dh + VTILE_B;
#pragma unroll
            for (int i = 0; i < 4; i++) {
                CP_ASYNC16(dh + i * 16, sh + i * 16);
                CP_ASYNC16(dl + i * 16, sl + i * 16);
            }
        }
    };

    {
        int row = tid >> 1, part = tid & 1;
        const char* s0 = (const char*)(gQh + (size_t)row * 128) + part * 128;
        const char* s1 = (const char*)(gQl + (size_t)row * 128) + part * 128;
        uint32_t d0 = sQh + (uint32_t)row * FK_ROW + part * 128;
        uint32_t d1 = sQl + (uint32_t)row * FK_ROW + part * 128;
#pragma unroll
        for (int i = 0; i < 8; i++) {
            CP_ASYNC16(d0 + i * 16, s0 + i * 16);
            CP_ASYNC16(d1 + i * 16, s1 + i * 16);
        }
    }
    load_stage(0, 0);
    CP_COMMIT();
    load_stage(1, 1);
    CP_COMMIT();

    float m0 = -INFINITY, m1 = -INFINITY, l0 = 0.f, l1 = 0.f;
    float oacc[16][4];
#pragma unroll
    for (int f = 0; f < 16; f++)
#pragma unroll
        for (int q = 0; q < 4; q++) oacc[f][q] = 0.f;

    const int l8  = lane & 7;
    const int grp = lane >> 3;
    const uint32_t brow = (uint32_t)(l8 + ((grp & 2) ? 8 : 0));
    const uint32_t bksel = (grp & 1) ? 16u : 0u;

    for (int kt = 0; kt < nkt; kt++) {
        if (kt < nkt - 1) { CP_WAIT1(); } else { CP_WAIT0(); }
        __syncthreads();

        const uint32_t stK = stg0 + (uint32_t)(kt & 1) * STAGE_B;
        const uint32_t stKh = stK, stKl = stK + KTILE_B;
        const uint32_t stVh = stK + 2u * KTILE_B, stVl = stVh + VTILE_B;

        // ---- S = Q K^T ----
        float s[8][4];
#pragma unroll
        for (int j = 0; j < 8; j++)
#pragma unroll
            for (int q = 0; q < 4; q++) s[j][q] = 0.f;

#pragma unroll
        for (int ks = 0; ks < 8; ks++) {
            uint32_t arow = (uint32_t)(wid * 16 + (lane & 15));
            uint32_t acol = (uint32_t)(ks * 32 + (lane >> 4) * 16);
            uint32_t aqh[4], aql[4];
            LDSM_X4(aqh, sQh + arow * FK_ROW + acol);
            LDSM_X4(aql, sQl + arow * FK_ROW + acol);

            uint32_t bcol = (uint32_t)(ks * 32) + bksel;
#pragma unroll
            for (int g = 0; g < 4; g += 2) {
                uint32_t nrow0 = (uint32_t)(g * 16) + brow;
                uint32_t nrow1 = nrow0 + 16;
                uint32_t bh0[4], bl0[4], bh1[4], bl1[4];
                LDSM_X4(bh0, stKh + nrow0 * FK_ROW + bcol);
                LDSM_X4(bl0, stKl + nrow0 * FK_ROW + bcol);
                LDSM_X4(bh1, stKh + nrow1 * FK_ROW + bcol);
                LDSM_X4(bl1, stKl + nrow1 * FK_ROW + bcol);
                // pass hh
                MMA16816(s[2 * g],     aqh, bh0[0], bh0[1]);
                MMA16816(s[2 * g + 1], aqh, bh0[2], bh0[3]);
                MMA16816(s[2 * g + 2], aqh, bh1[0], bh1[1]);
                MMA16816(s[2 * g + 3], aqh, bh1[2], bh1[3]);
                // pass hl
                MMA16816(s[2 * g],     aqh, bl0[0], bl0[1]);
                MMA16816(s[2 * g + 1], aqh, bl0[2], bl0[3]);
                MMA16816(s[2 * g + 2], aqh, bl1[0], bl1[1]);
                MMA16816(s[2 * g + 3], aqh, bl1[2], bl1[3]);
                // pass lh
                MMA16816(s[2 * g],     aql, bh0[0], bh0[1]);
                MMA16816(s[2 * g + 1], aql, bh0[2], bh0[3]);
                MMA16816(s[2 * g + 2], aql, bh1[0], bh1[1]);
                MMA16816(s[2 * g + 3], aql, bh1[2], bh1[3]);
            }
        }

        // ---- causal mask (diagonal tiles only) ----
        if (kt >= 2 * qt) {
            int grow0 = qt * 128 + wid * 16 + (lane >> 2);
            int gc0 = kt * 64 + (lane & 3) * 2;
#pragma unroll
            for (int j = 0; j < 8; j++) {
                int c = gc0 + j * 8;
                if (c     > grow0)     s[j][0] = -1e9f;
                if (c + 1 > grow0)     s[j][1] = -1e9f;
                if (c     > grow0 + 8) s[j][2] = -1e9f;
                if (c + 1 > grow0 + 8) s[j][3] = -1e9f;
            }
        }

        // ---- online softmax ----
        float mt0 = -INFINITY, mt1 = -INFINITY;
#pragma unroll
        for (int j = 0; j < 8; j++) {
            mt0 = fmaxf(mt0, fmaxf(s[j][0], s[j][1]));
            mt1 = fmaxf(mt1, fmaxf(s[j][2], s[j][3]));
        }
        mt0 = fmaxf(mt0, __shfl_xor_sync(0xffffffffu, mt0, 1));
        mt0 = fmaxf(mt0, __shfl_xor_sync(0xffffffffu, mt0, 2));
        mt1 = fmaxf(mt1, __shfl_xor_sync(0xffffffffu, mt1, 1));
        mt1 = fmaxf(mt1, __shfl_xor_sync(0xffffffffu, mt1, 2));

        float mn0 = fmaxf(m0, mt0), mn1 = fmaxf(m1, mt1);
        float corr0 = __expf(m0 - mn0), corr1 = __expf(m1 - mn1);
        m0 = mn0; m1 = mn1;

        float rs0 = 0.f, rs1 = 0.f;
#pragma unroll
        for (int j = 0; j < 8; j++) {
            s[j][0] = __expf(s[j][0] - mn0);
            s[j][1] = __expf(s[j][1] - mn0);
            s[j][2] = __expf(s[j][2] - mn1);
            s[j][3] = __expf(s[j][3] - mn1);
            rs0 += s[j][0] + s[j][1];
            rs1 += s[j][2] + s[j][3];
        }
        rs0 += __shfl_xor_sync(0xffffffffu, rs0, 1);
        rs0 += __shfl_xor_sync(0xffffffffu, rs0, 2);
        rs1 += __shfl_xor_sync(0xffffffffu, rs1, 1);
        rs1 += __shfl_xor_sync(0xffffffffu, rs1, 2);
        l0 = l0 * corr0 + rs0;
        l1 = l1 * corr1 + rs1;

#pragma unroll
        for (int f = 0; f < 16; f++) {
            oacc[f][0] *= corr0; oacc[f][1] *= corr0;
            oacc[f][2] *= corr1; oacc[f][3] *= corr1;
        }

        // ---- O += P V ----
#pragma unroll
        for (int g = 0; g < 4; g++) {
            const int f0 = 2 * g, f1 = 2 * g + 1;
            uint32_t pah[4], pal[4];
            pah[0] = pack_bf2(s[f0][0], s[f0][1]);
            pah[1] = pack_bf2(s[f0][2], s[f0][3]);
            pah[2] = pack_bf2(s[f1][0], s[f1][1]);
            pah[3] = pack_bf2(s[f1][2], s[f1][3]);
            pal[0] = pack_bf2(s[f0][0] - bf_round(s[f0][0]), s[f0][1] - bf_round(s[f0][1]));
            pal[1] = pack_bf2(s[f0][2] - bf_round(s[f0][2]), s[f0][3] - bf_round(s[f0][3]));
            pal[2] = pack_bf2(s[f1][0] - bf_round(s[f1][0]), s[f1][1] - bf_round(s[f1][1]));
            pal[3] = pack_bf2(s[f1][2] - bf_round(s[f1][2]), s[f1][3] - bf_round(s[f1][3]));

            uint32_t bco = (uint32_t)(g * 32) + bksel;
#pragma unroll
            for (int nb = 0; nb < 8; nb += 2) {
                uint32_t nrow0 = (uint32_t)(nb * 16) + brow;
                uint32_t nrow1 = nrow0 + 16;
                uint32_t vh0[4], vl0[4], vh1[4], vl1[4];
                LDSM_X4(vh0, stVh + nrow0 * FV_ROW + bco);
                LDSM_X4(vl0, stVl + nrow0 * FV_ROW + bco);
                LDSM_X4(vh1, stVh + nrow1 * FV_ROW + bco);
                LDSM_X4(vl1, stVl + nrow1 * FV_ROW + bco);
                // pass hh
                MMA16816(oacc[2 * nb],     pah, vh0[0], vh0[1]);
                MMA16816(oacc[2 * nb + 1], pah, vh0[2], vh0[3]);
                MMA16816(oacc[2 * nb + 2], pah, vh1[0], vh1[1]);
                MMA16816(oacc[2 * nb + 3], pah, vh1[2], vh1[3]);
                // pass hl
                MMA16816(oacc[2 * nb],     pah, vl0[0], vl0[1]);
                MMA16816(oacc[2 * nb + 1], pah, vl0[2], vl0[3]);
                MMA16816(oacc[2 * nb + 2], pah, vl1[0], vl1[1]);
                MMA16816(oacc[2 * nb + 3], pah, vl1[2], vl1[3]);
                // pass lh
                MMA16816(oacc[2 * nb],     pal, vh0[0], vh0[1]);
                MMA16816(oacc[2 * nb + 1], pal, vh0[2], vh0[3]);
                MMA16816(oacc[2 * nb + 2], pal, vh1[0], vh1[1]);
                MMA16816(oacc[2 * nb + 3], pal, vh1[2], vh1[3]);
            }
        }

        __syncthreads();
        if (kt + 2 < nkt) {
            load_stage(kt + 2, kt & 1);
            CP_COMMIT();
        }
    }

    // ---- epilogue: write ctx directly as bf16 hi/lo (fused split) ----
    float inv0 = 1.0f / l0, inv1 = 1.0f / l1;
    int trow = qt * 128 + wid * 16 + (lane >> 2);
    int c2 = (lane & 3) * 2;
    size_t base0 = ((size_t)(b * 2048 + trow)) * 2048 + h * 128;
    size_t base1 = base0 + (size_t)8 * 2048;
#pragma unroll
    for (int f = 0; f < 16; f++) {
        int col = f * 8 + c2;
        float y00 = oacc[f][0] * inv0, y01 = oacc[f][1] * inv0;
        float y10 = oacc[f][2] * inv1, y11 = oacc[f][3] * inv1;
        float h00 = bf_round(y00), h01 = bf_round(y01);
        float h10 = bf_round(y10), h11 = bf_round(y11);
        *(uint32_t*)(ch + base0 + col) = pack_bf2(h00, h01);
        *(uint32_t*)(cl + base0 + col) = pack_bf2(y00 - h00, y01 - h01);
        *(uint32_t*)(ch + base1 + col) = pack_bf2(h10, h11);
        *(uint32_t*)(cl + base1 + col) = pack_bf2(y10 - h10, y11 - h11);
    }
}

// ================= launch =================
extern "C" void kernel_launch(void* const* d_in, const int* in_sizes, int n_in,
                              void* d_out, int out_size)
{
    const float* x   = (const float*)d_in[0];
    const int*   pos = (const int*)d_in[1];
    const float* wq  = (const float*)d_in[2];
    const float* wk  = (const float*)d_in[3];
    const float* wv  = (const float*)d_in[4];
    const float* wo  = (const float*)d_in[5];
    float* out = (float*)d_out;

    float *Qp, *Kp, *Vp;
    cudaGetSymbolAddress((void**)&Qp, g_Q);
    cudaGetSymbolAddress((void**)&Kp, g_K);
    cudaGetSymbolAddress((void**)&Vp, g_V);

    __nv_bfloat16 *xh, *xl, *wqh, *wql, *wkh, *wkl, *wvh, *wvl, *woh, *wol, *ch, *cl;
    cudaGetSymbolAddress((void**)&xh,  g_xh);  cudaGetSymbolAddress((void**)&xl,  g_xl);
    cudaGetSymbolAddress((void**)&wqh, g_wqh); cudaGetSymbolAddress((void**)&wql, g_wql);
    cudaGetSymbolAddress((void**)&wkh, g_wkh); cudaGetSymbolAddress((void**)&wkl, g_wkl);
    cudaGetSymbolAddress((void**)&wvh, g_wvh); cudaGetSymbolAddress((void**)&wvl, g_wvl);
    cudaGetSymbolAddress((void**)&woh, g_woh); cudaGetSymbolAddress((void**)&wol, g_wol);
    cudaGetSymbolAddress((void**)&ch,  g_ch);  cudaGetSymbolAddress((void**)&cl,  g_cl);

    __nv_bfloat16 *qbh, *qbl, *kbh, *kbl, *vth, *vtl;
    cudaGetSymbolAddress((void**)&qbh, g_qbh); cudaGetSymbolAddress((void**)&qbl, g_qbl);
    cudaGetSymbolAddress((void**)&kbh, g_kbh); cudaGetSymbolAddress((void**)&kbl, g_kbl);
    cudaGetSymbolAddress((void**)&vth, g_vth); cudaGetSymbolAddress((void**)&vtl, g_vtl);

    cudaFuncSetAttribute(gemm_qkv, cudaFuncAttributeMaxDynamicSharedMemorySize, GEMM_SMEM);
    cudaFuncSetAttribute(gemm_mma, cudaFuncAttributeMaxDynamicSharedMemorySize, GEMM_SMEM);
    cudaFuncSetAttribute(flash_mma, cudaFuncAttributeMaxDynamicSharedMemorySize, FA2_SMEM);

    // bf16 hi/lo splits
    split_bf16<<<(4096 * 2048 / 4) / 256, 256>>>(x,  xh,  xl,  4096 * 2048 / 4);
    split_bf16<<<(2048 * 2048 / 4) / 256, 256>>>(wq, wqh, wql, 2048 * 2048 / 4);
    split_bf16<<<(512  * 2048 / 4) / 256, 256>>>(wk, wkh, wkl, 512 * 2048 / 4);
    split_bf16<<<(512  * 2048 / 4) / 256, 256>>>(wv, wvh, wvl, 512 * 2048 / 4);
    split_bf16<<<(2048 * 2048 / 4) / 256, 256>>>(wo, woh, wol, 2048 * 2048 / 4);

    // fused QKV projection (tensor cores)
    gemm_qkv<<<dim3(24, 32), 256, GEMM_SMEM>>>(xh, xl, wqh, wql, wkh, wkl, wvh, wvl,
                                               Qp, Kp, Vp);

    // RoPE -> bf16 hi/lo head-major (Q pre-scaled); V -> transposed bf16 hi/lo
    rope_q_bf<<<16384, 256>>>(Qp, pos, qbh, qbl);
    rope_k_bf<<<4096, 256>>>(Kp, pos, kbh, kbl);
    prep_v<<<dim3(32, 4, 2), 256>>>(Vp, vth, vtl);

    // causal GQA attention on tensor cores; epilogue writes bf16 hi/lo ctx
    flash_mma<<<dim3(16, 16, 2), 256, FA2_SMEM>>>(qbh, qbl, kbh, kbl, vth, vtl, ch, cl);

    // O projection (tensor cores)
    gemm_mma<<<dim3(16, 32), 256, GEMM_SMEM>>>(ch, cl, woh, wol, out, 2048, 2048);
}

// round 14
// speedup vs baseline: 3.1315x; 1.3925x over previous
#include <cuda_runtime.h>
#include <cuda_bf16.h>
#include <cuda_fp16.h>
#include <math.h>
#include <cstdint>

// ================= helpers =================
__device__ __forceinline__ uint32_t smem_u32(const void* p) {
    uint32_t a;
    asm("{ .reg .u64 t; cvta.to.shared.u64 t, %1; cvt.u32.u64 %0, t; }" : "=r"(a) : "l"(p));
    return a;
}

#define CP_ASYNC16(dst, src) \
    asm volatile("cp.async.cg.shared.global [%0], [%1], 16;" :: "r"(dst), "l"(src))
#define CP_COMMIT() asm volatile("cp.async.commit_group;" ::: "memory")
#define CP_WAIT2()  asm volatile("cp.async.wait_group 2;" ::: "memory")
#define CP_WAIT1()  asm volatile("cp.async.wait_group 1;" ::: "memory")
#define CP_WAIT0()  asm volatile("cp.async.wait_group 0;" ::: "memory")

#define LDSM_X4(r, addr) \
    asm volatile("ldmatrix.sync.aligned.m8n8.x4.shared.b16 {%0,%1,%2,%3}, [%4];" \
        : "=r"((r)[0]), "=r"((r)[1]), "=r"((r)[2]), "=r"((r)[3]) : "r"(addr))
#define MMA16816(d, a, b0, b1) \
    asm volatile("mma.sync.aligned.m16n8k16.row.col.f32.bf16.bf16.f32 " \
        "{%0,%1,%2,%3}, {%4,%5,%6,%7}, {%8,%9}, {%0,%1,%2,%3};" \
        : "+f"((d)[0]), "+f"((d)[1]), "+f"((d)[2]), "+f"((d)[3]) \
        : "r"((a)[0]), "r"((a)[1]), "r"((a)[2]), "r"((a)[3]), "r"(b0), "r"(b1))
#define MMAF16(d, a, b0, b1) \
    asm volatile("mma.sync.aligned.m16n8k16.row.col.f32.f16.f16.f32 " \
        "{%0,%1,%2,%3}, {%4,%5,%6,%7}, {%8,%9}, {%0,%1,%2,%3};" \
        : "+f"((d)[0]), "+f"((d)[1]), "+f"((d)[2]), "+f"((d)[3]) \
        : "r"((a)[0]), "r"((a)[1]), "r"((a)[2]), "r"((a)[3]), "r"(b0), "r"(b1))

__device__ __forceinline__ uint32_t pack_bf2(float lo, float hi) {
    uint32_t r;
    asm("cvt.rn.bf16x2.f32 %0, %1, %2;" : "=r"(r) : "f"(hi), "f"(lo));
    return r;
}
__device__ __forceinline__ float bf_round(float x) {
    return __bfloat162float(__float2bfloat16(x));
}

// ================= scratch (no allocations allowed) =================
__device__ float g_Q[4096 * 2048];
__device__ float g_K[4096 * 512];
__device__ float g_V[4096 * 512];

// fp16 GEMM operands
__device__ __half g_xh16[4096 * 2048];
__device__ __half g_xl16[4096 * 2048];
__device__ __half g_wq16[2048 * 2048];
__device__ __half g_wk16[512 * 2048];
__device__ __half g_wv16[512 * 2048];
__device__ __half g_wo16[2048 * 2048];
__device__ __half g_ch16[4096 * 2048];
__device__ __half g_cl16[4096 * 2048];

// attention operands (head-major, bf16 hi/lo 3-pass path)
__device__ __nv_bfloat16 g_qbh[2 * 16 * 2048 * 128];
__device__ __nv_bfloat16 g_qbl[2 * 16 * 2048 * 128];
__device__ __nv_bfloat16 g_kbh[2 * 4 * 2048 * 128];
__device__ __nv_bfloat16 g_kbl[2 * 4 * 2048 * 128];
__device__ __nv_bfloat16 g_vth[2 * 4 * 128 * 2048];
__device__ __nv_bfloat16 g_vtl[2 * 4 * 128 * 2048];

// ================= fp32 -> fp16 conversions =================
__global__ __launch_bounds__(256) void split_fp16(const float* __restrict__ in,
                                                  __half* __restrict__ hi,
                                                  __half* __restrict__ lo,
                                                  int n4)
{
    int i = blockIdx.x * 256 + threadIdx.x;
    if (i >= n4) return;
    float4 v = ((const float4*)in)[i];
    __half h0 = __float2half_rn(v.x);
    __half h1 = __float2half_rn(v.y);
    __half h2 = __float2half_rn(v.z);
    __half h3 = __float2half_rn(v.w);
    ((__half2*)hi)[2 * i]     = __half2(h0, h1);
    ((__half2*)hi)[2 * i + 1] = __half2(h2, h3);
    ((__half2*)lo)[2 * i]     = __half2(__float2half_rn(v.x - __half2float(h0)),
                                        __float2half_rn(v.y - __half2float(h1)));
    ((__half2*)lo)[2 * i + 1] = __half2(__float2half_rn(v.z - __half2float(h2)),
                                        __float2half_rn(v.w - __half2float(h3)));
}

__global__ __launch_bounds__(256) void conv_fp16(const float* __restrict__ in,
                                                 __half* __restrict__ out,
                                                 int n4)
{
    int i = blockIdx.x * 256 + threadIdx.x;
    if (i >= n4) return;
    float4 v = ((const float4*)in)[i];
    ((__half2*)out)[2 * i]     = __floats2half2_rn(v.x, v.y);
    ((__half2*)out)[2 * i + 1] = __floats2half2_rn(v.z, v.w);
}

// ================= fp16 2-pass GEMM: C = (Ah+Al)[M,K] * B16[N,K]^T =================
// CTA 128x128, 8 warps (4x2), warp 32x64, K-chunk 32, 3-stage cp.async.
// 3 operand tiles/stage (Ah, Al, B); 64 MMAs + 16 LDSM per warp per chunk.
#define TILE_B   (128 * 80)
#define BUF2_B   (3 * TILE_B)            // 30720
#define NSTAGE   3
#define GEMM2_SMEM (NSTAGE * BUF2_B)     // 92160

__device__ __forceinline__ void gemm_body2(
    const __half* __restrict__ Ah, const __half* __restrict__ Al,
    const __half* __restrict__ B,
    float* __restrict__ C, int Kdim, int ldc, int rowC, int colC, char* smptr)
{
    const uint32_t sbase = smem_u32(smptr);
    const int tid  = threadIdx.x;
    const int wid  = tid >> 5;
    const int lane = tid & 31;

    const int NC = Kdim >> 5;

    auto load_chunk = [&](int c, int stage) {
        const int kc = c << 5;
        const uint32_t stg = sbase + (uint32_t)stage * BUF2_B;
#pragma unroll
        for (int i = tid; i < 384; i += 256) {
            int t = i >> 7, row = i & 127;
            const __half* gs = (t == 0) ? Ah : (t == 1) ? Al : B;
            int rb = (t < 2) ? rowC : colC;
            const char* src = (const char*)(gs + (size_t)(rb + row) * Kdim + kc);
            uint32_t dst = stg + (uint32_t)t * TILE_B + (uint32_t)row * 80u;
#pragma unroll
            for (int cc = 0; cc < 4; cc++)
                CP_ASYNC16(dst + cc * 16, src + cc * 16);
        }
    };

    load_chunk(0, 0); CP_COMMIT();
    load_chunk(1, 1); CP_COMMIT();

    const int warp_m = wid & 3;
    const int warp_n = wid >> 2;

    float acc[2][8][4];
#pragma unroll
    for (int mf = 0; mf < 2; mf++)
#pragma unroll
        for (int j = 0; j < 8; j++)
#pragma unroll
            for (int q = 0; q < 4; q++) acc[mf][j][q] = 0.f;

    const int l8  = lane & 7;
    const int grp = lane >> 3;
    const uint32_t brow_off = (uint32_t)(l8 + ((grp & 2) ? 8 : 0));
    const uint32_t bsel     = (grp & 1) ? 16u : 0u;

    for (int c = 0; c < NC; c++) {
        if (c + 2 < NC) {
            load_chunk(c + 2, (c + 2) % NSTAGE);
            CP_COMMIT();
            CP_WAIT2();
        } else if (c + 1 < NC) {
            CP_WAIT1();
        } else {
            CP_WAIT0();
        }
        __syncthreads();

        const uint32_t buf = sbase + (uint32_t)(c % NSTAGE) * BUF2_B;
        const uint32_t sAh = buf;
        const uint32_t sAl = buf + TILE_B;
        const uint32_t sB  = buf + 2 * TILE_B;

#pragma unroll
        for (int ks = 0; ks < 2; ks++) {
            const uint32_t kb = (uint32_t)(ks * 32);

            uint32_t a_h[2][4], a_l[2][4];
#pragma unroll
            for (int mf = 0; mf < 2; mf++) {
                uint32_t row = (uint32_t)(warp_m * 32 + mf * 16 + (lane & 15));
                uint32_t col = (uint32_t)((lane >> 4) * 16) + kb;
                LDSM_X4(a_h[mf], sAh + row * 80u + col);
                LDSM_X4(a_l[mf], sAl + row * 80u + col);
            }

            const uint32_t bcol = kb + bsel;
#pragma unroll
            for (int g = 0; g < 4; g += 2) {
                uint32_t nrow0 = (uint32_t)(warp_n * 64 + g * 16) + brow_off;
                uint32_t nrow1 = nrow0 + 16;
                uint32_t b0[4], b1[4];
                LDSM_X4(b0, sB + nrow0 * 80u + bcol);
                LDSM_X4(b1, sB + nrow1 * 80u + bcol);

                // pass hi (round-robin over 8 accumulators)
                MMAF16(acc[0][2 * g],     a_h[0], b0[0], b0[1]);
                MMAF16(acc[0][2 * g + 1], a_h[0], b0[2], b0[3]);
                MMAF16(acc[0][2 * g + 2], a_h[0], b1[0], b1[1]);
                MMAF16(acc[0][2 * g + 3], a_h[0], b1[2], b1[3]);
                MMAF16(acc[1][2 * g],     a_h[1], b0[0], b0[1]);
                MMAF16(acc[1][2 * g + 1], a_h[1], b0[2], b0[3]);
                MMAF16(acc[1][2 * g + 2], a_h[1], b1[0], b1[1]);
                MMAF16(acc[1][2 * g + 3], a_h[1], b1[2], b1[3]);
                // pass lo
                MMAF16(acc[0][2 * g],     a_l[0], b0[0], b0[1]);
                MMAF16(acc[0][2 * g + 1], a_l[0], b0[2], b0[3]);
                MMAF16(acc[0][2 * g + 2], a_l[0], b1[0], b1[1]);
                MMAF16(acc[0][2 * g + 3], a_l[0], b1[2], b1[3]);
                MMAF16(acc[1][2 * g],     a_l[1], b0[0], b0[1]);
                MMAF16(acc[1][2 * g + 1], a_l[1], b0[2], b0[3]);
                MMAF16(acc[1][2 * g + 2], a_l[1], b1[0], b1[1]);
                MMAF16(acc[1][2 * g + 3], a_l[1], b1[2], b1[3]);
            }
        }
        __syncthreads();
    }

#pragma unroll
    for (int mf = 0; mf < 2; mf++) {
#pragma unroll
        for (int j = 0; j < 8; j++) {
            int r0 = rowC + warp_m * 32 + mf * 16 + (lane >> 2);
            int cc = colC + warp_n * 64 + j * 8 + (lane & 3) * 2;
            *(float2*)(C + (size_t)r0 * ldc + cc)       = make_float2(acc[mf][j][0], acc[mf][j][1]);
            *(float2*)(C + (size_t)(r0 + 8) * ldc + cc) = make_float2(acc[mf][j][2], acc[mf][j][3]);
        }
    }
}

__global__ __launch_bounds__(256)
void gemm_qkv2(const __half* __restrict__ xh, const __half* __restrict__ xl,
               const __half* __restrict__ wq, const __half* __restrict__ wk,
               const __half* __restrict__ wv,
               float* __restrict__ Qo, float* __restrict__ Ko, float* __restrict__ Vo)
{
    extern __shared__ char sm[];
    int bx = blockIdx.x;
    const __half* B; float* C; int ldc, colC;
    if (bx < 16)      { B = wq; C = Qo; ldc = 2048; colC = bx * 128; }
    else if (bx < 20) { B = wk; C = Ko; ldc = 512;  colC = (bx - 16) * 128; }
    else              { B = wv; C = Vo; ldc = 512;  colC = (bx - 20) * 128; }
    gemm_body2(xh, xl, B, C, 2048, ldc, blockIdx.y * 128, colC, sm);
}

__global__ __launch_bounds__(256)
void gemm_o2(const __half* __restrict__ Ah, const __half* __restrict__ Al,
             const __half* __restrict__ B, float* __restrict__ C, int Kdim, int ldc)
{
    extern __shared__ char sm[];
    gemm_body2(Ah, Al, B, C, Kdim, ldc, blockIdx.y * 128, blockIdx.x * 128, sm);
}

// ================= RoPE -> bf16 hi/lo, head-major =================
__global__ __launch_bounds__(256) void rope_q_bf(const float* __restrict__ Q,
                                                 const int* __restrict__ positions,
                                                 __nv_bfloat16* __restrict__ oh,
                                                 __nv_bfloat16* __restrict__ ol)
{
    int idx = blockIdx.x * 256 + threadIdx.x;
    int j = idx & 63;
    int t = (idx >> 6) & 2047;
    int h = (idx >> 17) & 15;
    int b = idx >> 21;
    float pos = (float)positions[b * 2048 + t];
    float inv_freq = powf(10000.0f, -(float)j * (1.0f / 64.0f));
    float ang = pos * inv_freq;
    float s, c;
    sincosf(ang, &s, &c);
    const float* p = Q + ((size_t)(b * 2048 + t)) * 2048 + h * 128;
    float x1 = p[j], x2 = p[j + 64];
    const float scale = 0.08838834764831845f;
    float y1 = (x1 * c - x2 * s) * scale;
    float y2 = (x1 * s + x2 * c) * scale;
    size_t ob = ((size_t)((b * 16 + h) * 2048 + t)) * 128;
    __nv_bfloat16 h1 = __float2bfloat16(y1);
    __nv_bfloat16 h2 = __float2bfloat16(y2);
    oh[ob + j]      = h1;
    oh[ob + j + 64] = h2;
    ol[ob + j]      = __float2bfloat16(y1 - __bfloat162float(h1));
    ol[ob + j + 64] = __float2bfloat16(y2 - __bfloat162float(h2));
}

__global__ __launch_bounds__(256) void rope_k_bf(const float* __restrict__ K,
                                                 const int* __restrict__ positions,
                                                 __nv_bfloat16* __restrict__ oh,
                                                 __nv_bfloat16* __restrict__ ol)
{
    int idx = blockIdx.x * 256 + threadIdx.x;
    int j = idx & 63;
    int t = (idx >> 6) & 2047;
    int h = (idx >> 17) & 3;
    int b = idx >> 19;
    float pos = (float)positions[b * 2048 + t];
    float inv_freq = powf(10000.0f, -(float)j * (1.0f / 64.0f));
    float ang = pos * inv_freq;
    float s, c;
    sincosf(ang, &s, &c);
    const float* p = K + ((size_t)(b * 2048 + t)) * 512 + h * 128;
    float x1 = p[j], x2 = p[j + 64];
    float y1 = x1 * c - x2 * s;
    float y2 = x1 * s + x2 * c;
    size_t ob = ((size_t)((b * 4 + h) * 2048 + t)) * 128;
    __nv_bfloat16 h1 = __float2bfloat16(y1);
    __nv_bfloat16 h2 = __float2bfloat16(y2);
    oh[ob + j]      = h1;
    oh[ob + j + 64] = h2;
    ol[ob + j]      = __float2bfloat16(y1 - __bfloat162float(h1));
    ol[ob + j + 64] = __float2bfloat16(y2 - __bfloat162float(h2));
}

// ================= V transpose -> bf16 hi/lo  [b][kvh][d][t] =================
__global__ __launch_bounds__(256) void prep_v(const float* __restrict__ V,
                                              __nv_bfloat16* __restrict__ vh,
                                              __nv_bfloat16* __restrict__ vl)
{
    __shared__ float tile[64][129];
    int tt = blockIdx.x, kvh = blockIdx.y, b = blockIdx.z;
    int tid = threadIdx.x, wid = tid >> 5, lane = tid & 31;

    for (int i = tid; i < 64 * 32; i += 256) {
        int r = i >> 5, c4 = (i & 31) << 2;
        float4 v = *(const float4*)(V + ((size_t)(b * 2048 + tt * 64 + r)) * 512 + kvh * 128 + c4);
        tile[r][c4 + 0] = v.x; tile[r][c4 + 1] = v.y;
        tile[r][c4 + 2] = v.z; tile[r][c4 + 3] = v.w;
    }
    __syncthreads();

#pragma unroll
    for (int pass = 0; pass < 4; pass++) {
        int d = pass * 32 + wid * 4 + (lane >> 3);
        int t0 = (lane & 7) * 8;
        size_t ob = ((size_t)((b * 4 + kvh) * 128 + d)) * 2048 + tt * 64 + t0;
        uint32_t hh[4], ll[4];
#pragma unroll
        for (int u = 0; u < 4; u++) {
            float x0 = tile[t0 + 2 * u][d];
            float x1 = tile[t0 + 2 * u + 1][d];
            __nv_bfloat16 a0 = __float2bfloat16(x0);
            __nv_bfloat16 a1 = __float2bfloat16(x1);
            __nv_bfloat162 hp(a0, a1);
            __nv_bfloat162 lp(__float2bfloat16(x0 - __bfloat162float(a0)),
                              __float2bfloat16(x1 - __bfloat162float(a1)));
            hh[u] = *(uint32_t*)&hp;
            ll[u] = *(uint32_t*)&lp;
        }
        *(uint4*)(vh + ob) = make_uint4(hh[0], hh[1], hh[2], hh[3]);
        *(uint4*)(vl + ob) = make_uint4(ll[0], ll[1], ll[2], ll[3]);
    }
}

// ================= flash attention on tensor cores (bf16 3-pass) =================
#define FK_ROW 272u
#define FV_ROW 144u
#define QTILE_B (128u * FK_ROW)
#define KTILE_B (64u * FK_ROW)
#define VTILE_B (128u * FV_ROW)
#define STAGE_B (2u * KTILE_B + 2u * VTILE_B)
#define FA2_SMEM (2u * QTILE_B + 2u * STAGE_B)

__global__ __launch_bounds__(256)
void flash_mma(const __nv_bfloat16* __restrict__ Qh, const __nv_bfloat16* __restrict__ Ql,
               const __nv_bfloat16* __restrict__ Kh, const __nv_bfloat16* __restrict__ Kl,
               const __nv_bfloat16* __restrict__ Vh, const __nv_bfloat16* __restrict__ Vl,
               __half* __restrict__ ch, __half* __restrict__ cl)
{
    extern __shared__ char sm[];
    const uint32_t sb = smem_u32(sm);
    const int qt = 15 - blockIdx.x;
    const int h = blockIdx.y, b = blockIdx.z;
    const int kvh = h >> 2;
    const int tid = threadIdx.x, wid = tid >> 5, lane = tid & 31;

    const uint32_t sQh = sb, sQl = sb + QTILE_B;
    const uint32_t stg0 = sb + 2u * QTILE_B;
    const int nkt = 2 * qt + 2;

    const __nv_bfloat16* gQh = Qh + ((size_t)((b * 16 + h) * 2048 + qt * 128)) * 128;
    const __nv_bfloat16* gQl = Ql + ((size_t)((b * 16 + h) * 2048 + qt * 128)) * 128;
    const __nv_bfloat16* gKh = Kh + ((size_t)((b * 4 + kvh) * 2048)) * 128;
    const __nv_bfloat16* gKl = Kl + ((size_t)((b * 4 + kvh) * 2048)) * 128;
    const __nv_bfloat16* gVh = Vh + ((size_t)((b * 4 + kvh) * 128)) * 2048;
    const __nv_bfloat16* gVl = Vl + ((size_t)((b * 4 + kvh) * 128)) * 2048;

    auto load_stage = [&](int kt, int s) {
        const uint32_t base = stg0 + (uint32_t)s * STAGE_B;
        {
            int row = tid >> 2, q4 = tid & 3;
            const char* sh = (const char*)(gKh + ((size_t)(kt * 64 + row)) * 128) + q4 * 64;
            const char* sl = (const char*)(gKl + ((size_t)(kt * 64 + row)) * 128) + q4 * 64;
            uint32_t dh = base + (uint32_t)row * FK_ROW + q4 * 64;
            uint32_t dl = dh + KTILE_B;
#pragma unroll
            for (int i = 0; i < 4; i++) {
                CP_ASYNC16(dh + i * 16, sh + i * 16);
                CP_ASYNC16(dl + i * 16, sl + i * 16);
            }
        }
        {
            int row = tid >> 1, hf = tid & 1;
            const char* sh = (const char*)(gVh + (size_t)row * 2048 + kt * 64) + hf * 64;
            const char* sl = (const char*)(gVl + (size_t)row * 2048 + kt * 64) + hf * 64;
            uint32_t dh = base + 2u * KTILE_B + (uint32_t)row * FV_ROW + hf * 64;
            uint32_t dl = dh + VTILE_B;
#pragma unroll
            for (int i = 0; i < 4; i++) {
                CP_ASYNC16(dh + i * 16, sh + i * 16);
                CP_ASYNC16(dl + i * 16, sl + i * 16);
            }
        }
    };

    {
        int row = tid >> 1, part = tid & 1;
        const char* s0 = (const char*)(gQh + (size_t)row * 128) + part * 128;
        const char* s1 = (const char*)(gQl + (size_t)row * 128) + part * 128;
        uint32_t d0 = sQh + (uint32_t)row * FK_ROW + part * 128;
        uint32_t d1 = sQl + (uint32_t)row * FK_ROW + part * 128;
#pragma unroll
        for (int i = 0; i < 8; i++) {
            CP_ASYNC16(d0 + i * 16, s0 + i * 16);
            CP_ASYNC16(d1 + i * 16, s1 + i * 16);
        }
    }
    load_stage(0, 0);
    CP_COMMIT();
    load_stage(1, 1);
    CP_COMMIT();

    float m0 = -INFINITY, m1 = -INFINITY, l0 = 0.f, l1 = 0.f;
    float oacc[16][4];
#pragma unroll
    for (int f = 0; f < 16; f++)
#pragma unroll
        for (int q = 0; q < 4; q++) oacc[f][q] = 0.f;

    const int l8  = lane & 7;
    const int grp = lane >> 3;
    const uint32_t brow = (uint32_t)(l8 + ((grp & 2) ? 8 : 0));
    const uint32_t bksel = (grp & 1) ? 16u : 0u;

    for (int kt = 0; kt < nkt; kt++) {
        if (kt < nkt - 1) { CP_WAIT1(); } else { CP_WAIT0(); }
        __syncthreads();

        const uint32_t stK = stg0 + (uint32_t)(kt & 1) * STAGE_B;
        const uint32_t stKh = stK, stKl = stK + KTILE_B;
        const uint32_t stVh = stK + 2u * KTILE_B, stVl = stVh + VTILE_B;

        float s[8][4];
#pragma unroll
        for (int j = 0; j < 8; j++)
#pragma unroll
            for (int q = 0; q < 4; q++) s[j][q] = 0.f;

#pragma unroll
        for (int ks = 0; ks < 8; ks++) {
            uint32_t arow = (uint32_t)(wid * 16 + (lane & 15));
            uint32_t acol = (uint32_t)(ks * 32 + (lane >> 4) * 16);
            uint32_t aqh[4], aql[4];
            LDSM_X4(aqh, sQh + arow * FK_ROW + acol);
            LDSM_X4(aql, sQl + arow * FK_ROW + acol);

            uint32_t bcol = (uint32_t)(ks * 32) + bksel;
#pragma unroll
            for (int g = 0; g < 4; g += 2) {
                uint32_t nrow0 = (uint32_t)(g * 16) + brow;
                uint32_t nrow1 = nrow0 + 16;
                uint32_t bh0[4], bl0[4], bh1[4], bl1[4];
                LDSM_X4(bh0, stKh + nrow0 * FK_ROW + bcol);
                LDSM_X4(bl0, stKl + nrow0 * FK_ROW + bcol);
                LDSM_X4(bh1, stKh + nrow1 * FK_ROW + bcol);
                LDSM_X4(bl1, stKl + nrow1 * FK_ROW + bcol);
                MMA16816(s[2 * g],     aqh, bh0[0], bh0[1]);
                MMA16816(s[2 * g + 1], aqh, bh0[2], bh0[3]);
                MMA16816(s[2 * g + 2], aqh, bh1[0], bh1[1]);
                MMA16816(s[2 * g + 3], aqh, bh1[2], bh1[3]);
                MMA16816(s[2 * g],     aqh, bl0[0], bl0[1]);
                MMA16816(s[2 * g + 1], aqh, bl0[2], bl0[3]);
                MMA16816(s[2 * g + 2], aqh, bl1[0], bl1[1]);
                MMA16816(s[2 * g + 3], aqh, bl1[2], bl1[3]);
                MMA16816(s[2 * g],     aql, bh0[0], bh0[1]);
                MMA16816(s[2 * g + 1], aql, bh0[2], bh0[3]);
                MMA16816(s[2 * g + 2], aql, bh1[0], bh1[1]);
                MMA16816(s[2 * g + 3], aql, bh1[2], bh1[3]);
            }
        }

        if (kt >= 2 * qt) {
            int grow0 = qt * 128 + wid * 16 + (lane >> 2);
            int gc0 = kt * 64 + (lane & 3) * 2;
#pragma unroll
            for (int j = 0; j < 8; j++) {
                int c = gc0 + j * 8;
                if (c     > grow0)     s[j][0] = -1e9f;
                if (c + 1 > grow0)     s[j][1] = -1e9f;
                if (c     > grow0 + 8) s[j][2] = -1e9f;
                if (c + 1 > grow0 + 8) s[j][3] = -1e9f;
            }
        }

        float mt0 = -INFINITY, mt1 = -INFINITY;
#pragma unroll
        for (int j = 0; j < 8; j++) {
            mt0 = fmaxf(mt0, fmaxf(s[j][0], s[j][1]));
            mt1 = fmaxf(mt1, fmaxf(s[j][2], s[j][3]));
        }
        mt0 = fmaxf(mt0, __shfl_xor_sync(0xffffffffu, mt0, 1));
        mt0 = fmaxf(mt0, __shfl_xor_sync(0xffffffffu, mt0, 2));
        mt1 = fmaxf(mt1, __shfl_xor_sync(0xffffffffu, mt1, 1));
        mt1 = fmaxf(mt1, __shfl_xor_sync(0xffffffffu, mt1, 2));

        float mn0 = fmaxf(m0, mt0), mn1 = fmaxf(m1, mt1);
        float corr0 = __expf(m0 - mn0), corr1 = __expf(m1 - mn1);
        m0 = mn0; m1 = mn1;

        float rs0 = 0.f, rs1 = 0.f;
#pragma unroll
        for (int j = 0; j < 8; j++) {
            s[j][0] = __expf(s[j][0] - mn0);
            s[j][1] = __expf(s[j][1] - mn0);
            s[j][2] = __expf(s[j][2] - mn1);
            s[j][3] = __expf(s[j][3] - mn1);
            rs0 += s[j][0] + s[j][1];
            rs1 += s[j][2] + s[j][3];
        }
        rs0 += __shfl_xor_sync(0xffffffffu, rs0, 1);
        rs0 += __shfl_xor_sync(0xffffffffu, rs0, 2);
        rs1 += __shfl_xor_sync(0xffffffffu, rs1, 1);
        rs1 += __shfl_xor_sync(0xffffffffu, rs1, 2);
        l0 = l0 * corr0 + rs0;
        l1 = l1 * corr1 + rs1;

#pragma unroll
        for (int f = 0; f < 16; f++) {
            oacc[f][0] *= corr0; oacc[f][1] *= corr0;
            oacc[f][2] *= corr1; oacc[f][3] *= corr1;
        }

#pragma unroll
        for (int g = 0; g < 4; g++) {
            const int f0 = 2 * g, f1 = 2 * g + 1;
            uint32_t pah[4], pal[4];
            pah[0] = pack_bf2(s[f0][0], s[f0][1]);
            pah[1] = pack_bf2(s[f0][2], s[f0][3]);
            pah[2] = pack_bf2(s[f1][0], s[f1][1]);
            pah[3] = pack_bf2(s[f1][2], s[f1][3]);
            pal[0] = pack_bf2(s[f0][0] - bf_round(s[f0][0]), s[f0][1] - bf_round(s[f0][1]));
            pal[1] = pack_bf2(s[f0][2] - bf_round(s[f0][2]), s[f0][3] - bf_round(s[f0][3]));
            pal[2] = pack_bf2(s[f1][0] - bf_round(s[f1][0]), s[f1][1] - bf_round(s[f1][1]));
            pal[3] = pack_bf2(s[f1][2] - bf_round(s[f1][2]), s[f1][3] - bf_round(s[f1][3]));

            uint32_t bco = (uint32_t)(g * 32) + bksel;
#pragma unroll
            for (int nb = 0; nb < 8; nb += 2) {
                uint32_t nrow0 = (uint32_t)(nb * 16) + brow;
                uint32_t nrow1 = nrow0 + 16;
                uint32_t vh0[4], vl0[4], vh1[4], vl1[4];
                LDSM_X4(vh0, stVh + nrow0 * FV_ROW + bco);
                LDSM_X4(vl0, stVl + nrow0 * FV_ROW + bco);
                LDSM_X4(vh1, stVh + nrow1 * FV_ROW + bco);
                LDSM_X4(vl1, stVl + nrow1 * FV_ROW + bco);
                MMA16816(oacc[2 * nb],     pah, vh0[0], vh0[1]);
                MMA16816(oacc[2 * nb + 1], pah, vh0[2], vh0[3]);
                MMA16816(oacc[2 * nb + 2], pah, vh1[0], vh1[1]);
                MMA16816(oacc[2 * nb + 3], pah, vh1[2], vh1[3]);
                MMA16816(oacc[2 * nb],     pah, vl0[0], vl0[1]);
                MMA16816(oacc[2 * nb + 1], pah, vl0[2], vl0[3]);
                MMA16816(oacc[2 * nb + 2], pah, vl1[0], vl1[1]);
                MMA16816(oacc[2 * nb + 3], pah, vl1[2], vl1[3]);
                MMA16816(oacc[2 * nb],     pal, vh0[0], vh0[1]);
                MMA16816(oacc[2 * nb + 1], pal, vh0[2], vh0[3]);
                MMA16816(oacc[2 * nb + 2], pal, vh1[0], vh1[1]);
                MMA16816(oacc[2 * nb + 3], pal, vh1[2], vh1[3]);
            }
        }

        __syncthreads();
        if (kt + 2 < nkt) {
            load_stage(kt + 2, kt & 1);
            CP_COMMIT();
        }
    }

    // ---- epilogue: write ctx as fp16 hi/lo for the 2-pass O-proj ----
    float inv0 = 1.0f / l0, inv1 = 1.0f / l1;
    int trow = qt * 128 + wid * 16 + (lane >> 2);
    int c2 = (lane & 3) * 2;
    size_t base0 = ((size_t)(b * 2048 + trow)) * 2048 + h * 128;
    size_t base1 = base0 + (size_t)8 * 2048;
#pragma unroll
    for (int f = 0; f < 16; f++) {
        int col = f * 8 + c2;
        float y00 = oacc[f][0] * inv0, y01 = oacc[f][1] * inv0;
        float y10 = oacc[f][2] * inv1, y11 = oacc[f][3] * inv1;
        __half h00 = __float2half_rn(y00), h01 = __float2half_rn(y01);
        __half h10 = __float2half_rn(y10), h11 = __float2half_rn(y11);
        *(__half2*)(ch + base0 + col) = __half2(h00, h01);
        *(__half2*)(cl + base0 + col) = __half2(__float2half_rn(y00 - __half2float(h00)),
                                                __float2half_rn(y01 - __half2float(h01)));
        *(__half2*)(ch + base1 + col) = __half2(h10, h11);
        *(__half2*)(cl + base1 + col) = __half2(__float2half_rn(y10 - __half2float(h10)),
                                                __float2half_rn(y11 - __half2float(h11)));
    }
}

// ================= launch =================
extern "C" void kernel_launch(void* const* d_in, const int* in_sizes, int n_in,
                              void* d_out, int out_size)
{
    const float* x   = (const float*)d_in[0];
    const int*   pos = (const int*)d_in[1];
    const float* wq  = (const float*)d_in[2];
    const float* wk  = (const float*)d_in[3];
    const float* wv  = (const float*)d_in[4];
    const float* wo  = (const float*)d_in[5];
    float* out = (float*)d_out;

    float *Qp, *Kp, *Vp;
    cudaGetSymbolAddress((void**)&Qp, g_Q);
    cudaGetSymbolAddress((void**)&Kp, g_K);
    cudaGetSymbolAddress((void**)&Vp, g_V);

    __half *xh, *xl, *wq16, *wk16, *wv16, *wo16, *ch, *cl;
    cudaGetSymbolAddress((void**)&xh,   g_xh16);
    cudaGetSymbolAddress((void**)&xl,   g_xl16);
    cudaGetSymbolAddress((void**)&wq16, g_wq16);
    cudaGetSymbolAddress((void**)&wk16, g_wk16);
    cudaGetSymbolAddress((void**)&wv16, g_wv16);
    cudaGetSymbolAddress((void**)&wo16, g_wo16);
    cudaGetSymbolAddress((void**)&ch,   g_ch16);
    cudaGetSymbolAddress((void**)&cl,   g_cl16);

    __nv_bfloat16 *qbh, *qbl, *kbh, *kbl, *vth, *vtl;
    cudaGetSymbolAddress((void**)&qbh, g_qbh); cudaGetSymbolAddress((void**)&qbl, g_qbl);
    cudaGetSymbolAddress((void**)&kbh, g_kbh); cudaGetSymbolAddress((void**)&kbl, g_kbl);
    cudaGetSymbolAddress((void**)&vth, g_vth); cudaGetSymbolAddress((void**)&vtl, g_vtl);

    cudaFuncSetAttribute(gemm_qkv2, cudaFuncAttributeMaxDynamicSharedMemorySize, GEMM2_SMEM);
    cudaFuncSetAttribute(gemm_o2, cudaFuncAttributeMaxDynamicSharedMemorySize, GEMM2_SMEM);
    cudaFuncSetAttribute(flash_mma, cudaFuncAttributeMaxDynamicSharedMemorySize, FA2_SMEM);

    // fp16 conversions: x split hi/lo; weights single fp16
    split_fp16<<<(4096 * 2048 / 4) / 256, 256>>>(x, xh, xl, 4096 * 2048 / 4);
    conv_fp16<<<(2048 * 2048 / 4) / 256, 256>>>(wq, wq16, 2048 * 2048 / 4);
    conv_fp16<<<(512  * 2048 / 4) / 256, 256>>>(wk, wk16, 512 * 2048 / 4);
    conv_fp16<<<(512  * 2048 / 4) / 256, 256>>>(wv, wv16, 512 * 2048 / 4);
    conv_fp16<<<(2048 * 2048 / 4) / 256, 256>>>(wo, wo16, 2048 * 2048 / 4);

    // fused QKV projection (fp16 2-pass tensor cores)
    gemm_qkv2<<<dim3(24, 32), 256, GEMM2_SMEM>>>(xh, xl, wq16, wk16, wv16, Qp, Kp, Vp);

    // RoPE -> bf16 hi/lo head-major (Q pre-scaled); V -> transposed bf16 hi/lo
    rope_q_bf<<<16384, 256>>>(Qp, pos, qbh, qbl);
    rope_k_bf<<<4096, 256>>>(Kp, pos, kbh, kbl);
    prep_v<<<dim3(32, 4, 2), 256>>>(Vp, vth, vtl);

    // causal GQA attention (bf16 3-pass); epilogue writes fp16 hi/lo ctx
    flash_mma<<<dim3(16, 16, 2), 256, FA2_SMEM>>>(qbh, qbl, kbh, kbl, vth, vtl, ch, cl);

    // O projection (fp16 2-pass tensor cores)
    gemm_o2<<<dim3(16, 32), 256, GEMM2_SMEM>>>(ch, cl, wo16, out, 2048, 2048);
}

// round 15
// speedup vs baseline: 3.4115x; 1.0894x over previous
#include <cuda_runtime.h>
#include <cuda_bf16.h>
#include <cuda_fp16.h>
#include <math.h>
#include <cstdint>

// ================= helpers =================
__device__ __forceinline__ uint32_t smem_u32(const void* p) {
    uint32_t a;
    asm("{ .reg .u64 t; cvta.to.shared.u64 t, %1; cvt.u32.u64 %0, t; }" : "=r"(a) : "l"(p));
    return a;
}

#define CP_ASYNC16(dst, src) \
    asm volatile("cp.async.cg.shared.global [%0], [%1], 16;" :: "r"(dst), "l"(src))
#define CP_COMMIT() asm volatile("cp.async.commit_group;" ::: "memory")
#define CP_WAIT2()  asm volatile("cp.async.wait_group 2;" ::: "memory")
#define CP_WAIT1()  asm volatile("cp.async.wait_group 1;" ::: "memory")
#define CP_WAIT0()  asm volatile("cp.async.wait_group 0;" ::: "memory")

#define LDSM_X4(r, addr) \
    asm volatile("ldmatrix.sync.aligned.m8n8.x4.shared.b16 {%0,%1,%2,%3}, [%4];" \
        : "=r"((r)[0]), "=r"((r)[1]), "=r"((r)[2]), "=r"((r)[3]) : "r"(addr))
#define MMAF16(d, a, b0, b1) \
    asm volatile("mma.sync.aligned.m16n8k16.row.col.f32.f16.f16.f32 " \
        "{%0,%1,%2,%3}, {%4,%5,%6,%7}, {%8,%9}, {%0,%1,%2,%3};" \
        : "+f"((d)[0]), "+f"((d)[1]), "+f"((d)[2]), "+f"((d)[3]) \
        : "r"((a)[0]), "r"((a)[1]), "r"((a)[2]), "r"((a)[3]), "r"(b0), "r"(b1))

__device__ __forceinline__ uint32_t pack_h2(float a, float b) {
    __half2 h = __floats2half2_rn(a, b);
    return *(uint32_t*)&h;
}

// ================= scratch (no allocations allowed) =================
__device__ float g_Q[4096 * 2048];
__device__ float g_K[4096 * 512];
__device__ float g_V[4096 * 512];

// fp16 GEMM operands
__device__ __half g_xh16[4096 * 2048];
__device__ __half g_xl16[4096 * 2048];
__device__ __half g_wq16[2048 * 2048];
__device__ __half g_wk16[512 * 2048];
__device__ __half g_wv16[512 * 2048];
__device__ __half g_wo16[2048 * 2048];
__device__ __half g_ch16[4096 * 2048];
__device__ __half g_cl16[4096 * 2048];

// attention operands (head-major, fp16)
__device__ __half g_qah[2 * 16 * 2048 * 128];   // Q hi
__device__ __half g_qal[2 * 16 * 2048 * 128];   // Q lo
__device__ __half g_ka16[2 * 4 * 2048 * 128];   // K single fp16
__device__ __half g_vth16[2 * 4 * 128 * 2048];  // V^T hi [b][kvh][d][t]
__device__ __half g_vtl16[2 * 4 * 128 * 2048];  // V^T lo

// ================= fp32 -> fp16 conversions =================
__global__ __launch_bounds__(256) void split_fp16(const float* __restrict__ in,
                                                  __half* __restrict__ hi,
                                                  __half* __restrict__ lo,
                                                  int n4)
{
    int i = blockIdx.x * 256 + threadIdx.x;
    if (i >= n4) return;
    float4 v = ((const float4*)in)[i];
    __half h0 = __float2half_rn(v.x);
    __half h1 = __float2half_rn(v.y);
    __half h2 = __float2half_rn(v.z);
    __half h3 = __float2half_rn(v.w);
    ((__half2*)hi)[2 * i]     = __half2(h0, h1);
    ((__half2*)hi)[2 * i + 1] = __half2(h2, h3);
    ((__half2*)lo)[2 * i]     = __half2(__float2half_rn(v.x - __half2float(h0)),
                                        __float2half_rn(v.y - __half2float(h1)));
    ((__half2*)lo)[2 * i + 1] = __half2(__float2half_rn(v.z - __half2float(h2)),
                                        __float2half_rn(v.w - __half2float(h3)));
}

__global__ __launch_bounds__(256) void conv_fp16(const float* __restrict__ in,
                                                 __half* __restrict__ out,
                                                 int n4)
{
    int i = blockIdx.x * 256 + threadIdx.x;
    if (i >= n4) return;
    float4 v = ((const float4*)in)[i];
    ((__half2*)out)[2 * i]     = __floats2half2_rn(v.x, v.y);
    ((__half2*)out)[2 * i + 1] = __floats2half2_rn(v.z, v.w);
}

// ================= fp16 2-pass GEMM: C = (Ah+Al)[M,K] * B16[N,K]^T =================
#define TILE_B   (128 * 80)
#define BUF2_B   (3 * TILE_B)
#define NSTAGE   3
#define GEMM2_SMEM (NSTAGE * BUF2_B)

__device__ __forceinline__ void gemm_body2(
    const __half* __restrict__ Ah, const __half* __restrict__ Al,
    const __half* __restrict__ B,
    float* __restrict__ C, int Kdim, int ldc, int rowC, int colC, char* smptr)
{
    const uint32_t sbase = smem_u32(smptr);
    const int tid  = threadIdx.x;
    const int wid  = tid >> 5;
    const int lane = tid & 31;

    const int NC = Kdim >> 5;

    auto load_chunk = [&](int c, int stage) {
        const int kc = c << 5;
        const uint32_t stg = sbase + (uint32_t)stage * BUF2_B;
#pragma unroll
        for (int i = tid; i < 384; i += 256) {
            int t = i >> 7, row = i & 127;
            const __half* gs = (t == 0) ? Ah : (t == 1) ? Al : B;
            int rb = (t < 2) ? rowC : colC;
            const char* src = (const char*)(gs + (size_t)(rb + row) * Kdim + kc);
            uint32_t dst = stg + (uint32_t)t * TILE_B + (uint32_t)row * 80u;
#pragma unroll
            for (int cc = 0; cc < 4; cc++)
                CP_ASYNC16(dst + cc * 16, src + cc * 16);
        }
    };

    load_chunk(0, 0); CP_COMMIT();
    load_chunk(1, 1); CP_COMMIT();

    const int warp_m = wid & 3;
    const int warp_n = wid >> 2;

    float acc[2][8][4];
#pragma unroll
    for (int mf = 0; mf < 2; mf++)
#pragma unroll
        for (int j = 0; j < 8; j++)
#pragma unroll
            for (int q = 0; q < 4; q++) acc[mf][j][q] = 0.f;

    const int l8  = lane & 7;
    const int grp = lane >> 3;
    const uint32_t brow_off = (uint32_t)(l8 + ((grp & 2) ? 8 : 0));
    const uint32_t bsel     = (grp & 1) ? 16u : 0u;

    for (int c = 0; c < NC; c++) {
        if (c + 2 < NC) {
            load_chunk(c + 2, (c + 2) % NSTAGE);
            CP_COMMIT();
            CP_WAIT2();
        } else if (c + 1 < NC) {
            CP_WAIT1();
        } else {
            CP_WAIT0();
        }
        __syncthreads();

        const uint32_t buf = sbase + (uint32_t)(c % NSTAGE) * BUF2_B;
        const uint32_t sAh = buf;
        const uint32_t sAl = buf + TILE_B;
        const uint32_t sB  = buf + 2 * TILE_B;

#pragma unroll
        for (int ks = 0; ks < 2; ks++) {
            const uint32_t kb = (uint32_t)(ks * 32);

            uint32_t a_h[2][4], a_l[2][4];
#pragma unroll
            for (int mf = 0; mf < 2; mf++) {
                uint32_t row = (uint32_t)(warp_m * 32 + mf * 16 + (lane & 15));
                uint32_t col = (uint32_t)((lane >> 4) * 16) + kb;
                LDSM_X4(a_h[mf], sAh + row * 80u + col);
                LDSM_X4(a_l[mf], sAl + row * 80u + col);
            }

            const uint32_t bcol = kb + bsel;
#pragma unroll
            for (int g = 0; g < 4; g += 2) {
                uint32_t nrow0 = (uint32_t)(warp_n * 64 + g * 16) + brow_off;
                uint32_t nrow1 = nrow0 + 16;
                uint32_t b0[4], b1[4];
                LDSM_X4(b0, sB + nrow0 * 80u + bcol);
                LDSM_X4(b1, sB + nrow1 * 80u + bcol);

                MMAF16(acc[0][2 * g],     a_h[0], b0[0], b0[1]);
                MMAF16(acc[0][2 * g + 1], a_h[0], b0[2], b0[3]);
                MMAF16(acc[0][2 * g + 2], a_h[0], b1[0], b1[1]);
                MMAF16(acc[0][2 * g + 3], a_h[0], b1[2], b1[3]);
                MMAF16(acc[1][2 * g],     a_h[1], b0[0], b0[1]);
                MMAF16(acc[1][2 * g + 1], a_h[1], b0[2], b0[3]);
                MMAF16(acc[1][2 * g + 2], a_h[1], b1[0], b1[1]);
                MMAF16(acc[1][2 * g + 3], a_h[1], b1[2], b1[3]);
                MMAF16(acc[0][2 * g],     a_l[0], b0[0], b0[1]);
                MMAF16(acc[0][2 * g + 1], a_l[0], b0[2], b0[3]);
                MMAF16(acc[0][2 * g + 2], a_l[0], b1[0], b1[1]);
                MMAF16(acc[0][2 * g + 3], a_l[0], b1[2], b1[3]);
                MMAF16(acc[1][2 * g],     a_l[1], b0[0], b0[1]);
                MMAF16(acc[1][2 * g + 1], a_l[1], b0[2], b0[3]);
                MMAF16(acc[1][2 * g + 2], a_l[1], b1[0], b1[1]);
                MMAF16(acc[1][2 * g + 3], a_l[1], b1[2], b1[3]);
            }
        }
        __syncthreads();
    }

#pragma unroll
    for (int mf = 0; mf < 2; mf++) {
#pragma unroll
        for (int j = 0; j < 8; j++) {
            int r0 = rowC + warp_m * 32 + mf * 16 + (lane >> 2);
            int cc = colC + warp_n * 64 + j * 8 + (lane & 3) * 2;
            *(float2*)(C + (size_t)r0 * ldc + cc)       = make_float2(acc[mf][j][0], acc[mf][j][1]);
            *(float2*)(C + (size_t)(r0 + 8) * ldc + cc) = make_float2(acc[mf][j][2], acc[mf][j][3]);
        }
    }
}

__global__ __launch_bounds__(256)
void gemm_qkv2(const __half* __restrict__ xh, const __half* __restrict__ xl,
               const __half* __restrict__ wq, const __half* __restrict__ wk,
               const __half* __restrict__ wv,
               float* __restrict__ Qo, float* __restrict__ Ko, float* __restrict__ Vo)
{
    extern __shared__ char sm[];
    int bx = blockIdx.x;
    const __half* B; float* C; int ldc, colC;
    if (bx < 16)      { B = wq; C = Qo; ldc = 2048; colC = bx * 128; }
    else if (bx < 20) { B = wk; C = Ko; ldc = 512;  colC = (bx - 16) * 128; }
    else              { B = wv; C = Vo; ldc = 512;  colC = (bx - 20) * 128; }
    gemm_body2(xh, xl, B, C, 2048, ldc, blockIdx.y * 128, colC, sm);
}

__global__ __launch_bounds__(256)
void gemm_o2(const __half* __restrict__ Ah, const __half* __restrict__ Al,
             const __half* __restrict__ B, float* __restrict__ C, int Kdim, int ldc)
{
    extern __shared__ char sm[];
    gemm_body2(Ah, Al, B, C, Kdim, ldc, blockIdx.y * 128, blockIdx.x * 128, sm);
}

// ================= RoPE -> fp16, head-major =================
// Q: scale folded, hi/lo split. out layout [b][h][t][128]
__global__ __launch_bounds__(256) void rope_q_f16(const float* __restrict__ Q,
                                                  const int* __restrict__ positions,
                                                  __half* __restrict__ oh,
                                                  __half* __restrict__ ol)
{
    int idx = blockIdx.x * 256 + threadIdx.x;
    int j = idx & 63;
    int t = (idx >> 6) & 2047;
    int h = (idx >> 17) & 15;
    int b = idx >> 21;
    float pos = (float)positions[b * 2048 + t];
    float inv_freq = powf(10000.0f, -(float)j * (1.0f / 64.0f));
    float ang = pos * inv_freq;
    float s, c;
    sincosf(ang, &s, &c);
    const float* p = Q + ((size_t)(b * 2048 + t)) * 2048 + h * 128;
    float x1 = p[j], x2 = p[j + 64];
    const float scale = 0.08838834764831845f;
    float y1 = (x1 * c - x2 * s) * scale;
    float y2 = (x1 * s + x2 * c) * scale;
    size_t ob = ((size_t)((b * 16 + h) * 2048 + t)) * 128;
    __half h1 = __float2half_rn(y1);
    __half h2 = __float2half_rn(y2);
    oh[ob + j]      = h1;
    oh[ob + j + 64] = h2;
    ol[ob + j]      = __float2half_rn(y1 - __half2float(h1));
    ol[ob + j + 64] = __float2half_rn(y2 - __half2float(h2));
}

// K: single fp16
__global__ __launch_bounds__(256) void rope_k_f16(const float* __restrict__ K,
                                                  const int* __restrict__ positions,
                                                  __half* __restrict__ ok)
{
    int idx = blockIdx.x * 256 + threadIdx.x;
    int j = idx & 63;
    int t = (idx >> 6) & 2047;
    int h = (idx >> 17) & 3;
    int b = idx >> 19;
    float pos = (float)positions[b * 2048 + t];
    float inv_freq = powf(10000.0f, -(float)j * (1.0f / 64.0f));
    float ang = pos * inv_freq;
    float s, c;
    sincosf(ang, &s, &c);
    const float* p = K + ((size_t)(b * 2048 + t)) * 512 + h * 128;
    float x1 = p[j], x2 = p[j + 64];
    size_t ob = ((size_t)((b * 4 + h) * 2048 + t)) * 128;
    ok[ob + j]      = __float2half_rn(x1 * c - x2 * s);
    ok[ob + j + 64] = __float2half_rn(x1 * s + x2 * c);
}

// ================= V transpose -> fp16 hi/lo  [b][kvh][d][t] =================
__global__ __launch_bounds__(256) void prep_v16(const float* __restrict__ V,
                                                __half* __restrict__ vh,
                                                __half* __restrict__ vl)
{
    __shared__ float tile[64][129];
    int tt = blockIdx.x, kvh = blockIdx.y, b = blockIdx.z;
    int tid = threadIdx.x, wid = tid >> 5, lane = tid & 31;

    for (int i = tid; i < 64 * 32; i += 256) {
        int r = i >> 5, c4 = (i & 31) << 2;
        float4 v = *(const float4*)(V + ((size_t)(b * 2048 + tt * 64 + r)) * 512 + kvh * 128 + c4);
        tile[r][c4 + 0] = v.x; tile[r][c4 + 1] = v.y;
        tile[r][c4 + 2] = v.z; tile[r][c4 + 3] = v.w;
    }
    __syncthreads();

#pragma unroll
    for (int pass = 0; pass < 4; pass++) {
        int d = pass * 32 + wid * 4 + (lane >> 3);
        int t0 = (lane & 7) * 8;
        size_t ob = ((size_t)((b * 4 + kvh) * 128 + d)) * 2048 + tt * 64 + t0;
        uint32_t hh[4], ll[4];
#pragma unroll
        for (int u = 0; u < 4; u++) {
            float x0 = tile[t0 + 2 * u][d];
            float x1 = tile[t0 + 2 * u + 1][d];
            __half a0 = __float2half_rn(x0);
            __half a1 = __float2half_rn(x1);
            __half2 hp(a0, a1);
            __half2 lp(__float2half_rn(x0 - __half2float(a0)),
                       __float2half_rn(x1 - __half2float(a1)));
            hh[u] = *(uint32_t*)&hp;
            ll[u] = *(uint32_t*)&lp;
        }
        *(uint4*)(vh + ob) = make_uint4(hh[0], hh[1], hh[2], hh[3]);
        *(uint4*)(vl + ob) = make_uint4(ll[0], ll[1], ll[2], ll[3]);
    }
}

// ================= flash attention on tensor cores (fp16 2-pass) =================
// S: Q hi/lo x K single. PV: P single x V hi/lo. 256 MMAs per warp per kt.
#define FK_ROW 272u
#define FV_ROW 144u
#define QTILE_B (128u * FK_ROW)                 // 34816
#define KTILE_B (64u * FK_ROW)                  // 17408
#define VTILE_B (128u * FV_ROW)                 // 18432
#define STAGE_B (KTILE_B + 2u * VTILE_B)        // 54272
#define FA3_SMEM (2u * QTILE_B + 2u * STAGE_B)  // 178176

__global__ __launch_bounds__(256)
void flash_mma(const __half* __restrict__ Qh, const __half* __restrict__ Ql,
               const __half* __restrict__ Kk,
               const __half* __restrict__ Vh, const __half* __restrict__ Vl,
               __half* __restrict__ ch, __half* __restrict__ cl)
{
    extern __shared__ char sm[];
    const uint32_t sb = smem_u32(sm);
    const int qt = 15 - blockIdx.x;          // heavy tiles first
    const int h = blockIdx.y, b = blockIdx.z;
    const int kvh = h >> 2;
    const int tid = threadIdx.x, wid = tid >> 5, lane = tid & 31;

    const uint32_t sQh = sb, sQl = sb + QTILE_B;
    const uint32_t stg0 = sb + 2u * QTILE_B;
    const int nkt = 2 * qt + 2;

    const __half* gQh = Qh + ((size_t)((b * 16 + h) * 2048 + qt * 128)) * 128;
    const __half* gQl = Ql + ((size_t)((b * 16 + h) * 2048 + qt * 128)) * 128;
    const __half* gK  = Kk + ((size_t)((b * 4 + kvh) * 2048)) * 128;
    const __half* gVh = Vh + ((size_t)((b * 4 + kvh) * 128)) * 2048;
    const __half* gVl = Vl + ((size_t)((b * 4 + kvh) * 128)) * 2048;

    auto load_stage = [&](int kt, int s) {
        const uint32_t base = stg0 + (uint32_t)s * STAGE_B;
        {   // K tile: 64 rows x 256B, single
            int row = tid >> 2, q4 = tid & 3;
            const char* sk = (const char*)(gK + ((size_t)(kt * 64 + row)) * 128) + q4 * 64;
            uint32_t dk = base + (uint32_t)row * FK_ROW + q4 * 64;
#pragma unroll
            for (int i = 0; i < 4; i++)
                CP_ASYNC16(dk + i * 16, sk + i * 16);
        }
        {   // V tiles: 128 rows x 128B, hi + lo
            int row = tid >> 1, hf = tid & 1;
            const char* sh = (const char*)(gVh + (size_t)row * 2048 + kt * 64) + hf * 64;
            const char* sl = (const char*)(gVl + (size_t)row * 2048 + kt * 64) + hf * 64;
            uint32_t dh = base + KTILE_B + (uint32_t)row * FV_ROW + hf * 64;
            uint32_t dl = dh + VTILE_B;
#pragma unroll
            for (int i = 0; i < 4; i++) {
                CP_ASYNC16(dh + i * 16, sh + i * 16);
                CP_ASYNC16(dl + i * 16, sl + i * 16);
            }
        }
    };

    // prologue: Q hi/lo + stage0 as group0, stage1 as group1
    {
        int row = tid >> 1, part = tid & 1;
        const char* s0 = (const char*)(gQh + (size_t)row * 128) + part * 128;
        const char* s1 = (const char*)(gQl + (size_t)row * 128) + part * 128;
        uint32_t d0 = sQh + (uint32_t)row * FK_ROW + part * 128;
        uint32_t d1 = sQl + (uint32_t)row * FK_ROW + part * 128;
#pragma unroll
        for (int i = 0; i < 8; i++) {
            CP_ASYNC16(d0 + i * 16, s0 + i * 16);
            CP_ASYNC16(d1 + i * 16, s1 + i * 16);
        }
    }
    load_stage(0, 0);
    CP_COMMIT();
    load_stage(1, 1);
    CP_COMMIT();

    float m0 = -INFINITY, m1 = -INFINITY, l0 = 0.f, l1 = 0.f;
    float oacc[16][4];
#pragma unroll
    for (int f = 0; f < 16; f++)
#pragma unroll
        for (int q = 0; q < 4; q++) oacc[f][q] = 0.f;

    const int l8  = lane & 7;
    const int grp = lane >> 3;
    const uint32_t brow = (uint32_t)(l8 + ((grp & 2) ? 8 : 0));
    const uint32_t bksel = (grp & 1) ? 16u : 0u;

    for (int kt = 0; kt < nkt; kt++) {
        if (kt < nkt - 1) { CP_WAIT1(); } else { CP_WAIT0(); }
        __syncthreads();

        const uint32_t stK = stg0 + (uint32_t)(kt & 1) * STAGE_B;
        const uint32_t stVh = stK + KTILE_B, stVl = stVh + VTILE_B;

        // ---- S = Q K^T : 2 passes (Qh·K + Ql·K) ----
        float s[8][4];
#pragma unroll
        for (int j = 0; j < 8; j++)
#pragma unroll
            for (int q = 0; q < 4; q++) s[j][q] = 0.f;

#pragma unroll
        for (int ks = 0; ks < 8; ks++) {
            uint32_t arow = (uint32_t)(wid * 16 + (lane & 15));
            uint32_t acol = (uint32_t)(ks * 32 + (lane >> 4) * 16);
            uint32_t aqh[4], aql[4];
            LDSM_X4(aqh, sQh + arow * FK_ROW + acol);
            LDSM_X4(aql, sQl + arow * FK_ROW + acol);

            uint32_t bcol = (uint32_t)(ks * 32) + bksel;
#pragma unroll
            for (int g = 0; g < 4; g += 2) {
                uint32_t nrow0 = (uint32_t)(g * 16) + brow;
                uint32_t nrow1 = nrow0 + 16;
                uint32_t b0[4], b1[4];
                LDSM_X4(b0, stK + nrow0 * FK_ROW + bcol);
                LDSM_X4(b1, stK + nrow1 * FK_ROW + bcol);
                // pass hi
                MMAF16(s[2 * g],     aqh, b0[0], b0[1]);
                MMAF16(s[2 * g + 1], aqh, b0[2], b0[3]);
                MMAF16(s[2 * g + 2], aqh, b1[0], b1[1]);
                MMAF16(s[2 * g + 3], aqh, b1[2], b1[3]);
                // pass lo
                MMAF16(s[2 * g],     aql, b0[0], b0[1]);
                MMAF16(s[2 * g + 1], aql, b0[2], b0[3]);
                MMAF16(s[2 * g + 2], aql, b1[0], b1[1]);
                MMAF16(s[2 * g + 3], aql, b1[2], b1[3]);
            }
        }

        // ---- causal mask (diagonal tiles only) ----
        if (kt >= 2 * qt) {
            int grow0 = qt * 128 + wid * 16 + (lane >> 2);
            int gc0 = kt * 64 + (lane & 3) * 2;
#pragma unroll
            for (int j = 0; j < 8; j++) {
                int c = gc0 + j * 8;
                if (c     > grow0)     s[j][0] = -1e9f;
                if (c + 1 > grow0)     s[j][1] = -1e9f;
                if (c     > grow0 + 8) s[j][2] = -1e9f;
                if (c + 1 > grow0 + 8) s[j][3] = -1e9f;
            }
        }

        // ---- online softmax ----
        float mt0 = -INFINITY, mt1 = -INFINITY;
#pragma unroll
        for (int j = 0; j < 8; j++) {
            mt0 = fmaxf(mt0, fmaxf(s[j][0], s[j][1]));
            mt1 = fmaxf(mt1, fmaxf(s[j][2], s[j][3]));
        }
        mt0 = fmaxf(mt0, __shfl_xor_sync(0xffffffffu, mt0, 1));
        mt0 = fmaxf(mt0, __shfl_xor_sync(0xffffffffu, mt0, 2));
        mt1 = fmaxf(mt1, __shfl_xor_sync(0xffffffffu, mt1, 1));
        mt1 = fmaxf(mt1, __shfl_xor_sync(0xffffffffu, mt1, 2));

        float mn0 = fmaxf(m0, mt0), mn1 = fmaxf(m1, mt1);
        float corr0 = __expf(m0 - mn0), corr1 = __expf(m1 - mn1);
        m0 = mn0; m1 = mn1;

        float rs0 = 0.f, rs1 = 0.f;
#pragma unroll
        for (int j = 0; j < 8; j++) {
            s[j][0] = __expf(s[j][0] - mn0);
            s[j][1] = __expf(s[j][1] - mn0);
            s[j][2] = __expf(s[j][2] - mn1);
            s[j][3] = __expf(s[j][3] - mn1);
            rs0 += s[j][0] + s[j][1];
            rs1 += s[j][2] + s[j][3];
        }
        rs0 += __shfl_xor_sync(0xffffffffu, rs0, 1);
        rs0 += __shfl_xor_sync(0xffffffffu, rs0, 2);
        rs1 += __shfl_xor_sync(0xffffffffu, rs1, 1);
        rs1 += __shfl_xor_sync(0xffffffffu, rs1, 2);
        l0 = l0 * corr0 + rs0;
        l1 = l1 * corr1 + rs1;

#pragma unroll
        for (int f = 0; f < 16; f++) {
            oacc[f][0] *= corr0; oacc[f][1] *= corr0;
            oacc[f][2] *= corr1; oacc[f][3] *= corr1;
        }

        // ---- O += P V : P single fp16, V hi/lo (2 passes) ----
#pragma unroll
        for (int g = 0; g < 4; g++) {
            const int f0 = 2 * g, f1 = 2 * g + 1;
            uint32_t pa[4];
            pa[0] = pack_h2(s[f0][0], s[f0][1]);
            pa[1] = pack_h2(s[f0][2], s[f0][3]);
            pa[2] = pack_h2(s[f1][0], s[f1][1]);
            pa[3] = pack_h2(s[f1][2], s[f1][3]);

            uint32_t bco = (uint32_t)(g * 32) + bksel;
#pragma unroll
            for (int nb = 0; nb < 8; nb += 2) {
                uint32_t nrow0 = (uint32_t)(nb * 16) + brow;
                uint32_t nrow1 = nrow0 + 16;
                uint32_t vh0[4], vl0[4], vh1[4], vl1[4];
                LDSM_X4(vh0, stVh + nrow0 * FV_ROW + bco);
                LDSM_X4(vl0, stVl + nrow0 * FV_ROW + bco);
                LDSM_X4(vh1, stVh + nrow1 * FV_ROW + bco);
                LDSM_X4(vl1, stVl + nrow1 * FV_ROW + bco);
                // pass hi
                MMAF16(oacc[2 * nb],     pa, vh0[0], vh0[1]);
                MMAF16(oacc[2 * nb + 1], pa, vh0[2], vh0[3]);
                MMAF16(oacc[2 * nb + 2], pa, vh1[0], vh1[1]);
                MMAF16(oacc[2 * nb + 3], pa, vh1[2], vh1[3]);
                // pass lo
                MMAF16(oacc[2 * nb],     pa, vl0[0], vl0[1]);
                MMAF16(oacc[2 * nb + 1], pa, vl0[2], vl0[3]);
                MMAF16(oacc[2 * nb + 2], pa, vl1[0], vl1[1]);
                MMAF16(oacc[2 * nb + 3], pa, vl1[2], vl1[3]);
            }
        }

        __syncthreads();
        if (kt + 2 < nkt) {
            load_stage(kt + 2, kt & 1);
            CP_COMMIT();
        }
    }

    // ---- epilogue: write ctx as fp16 hi/lo for the 2-pass O-proj ----
    float inv0 = 1.0f / l0, inv1 = 1.0f / l1;
    int trow = qt * 128 + wid * 16 + (lane >> 2);
    int c2 = (lane & 3) * 2;
    size_t base0 = ((size_t)(b * 2048 + trow)) * 2048 + h * 128;
    size_t base1 = base0 + (size_t)8 * 2048;
#pragma unroll
    for (int f = 0; f < 16; f++) {
        int col = f * 8 + c2;
        float y00 = oacc[f][0] * inv0, y01 = oacc[f][1] * inv0;
        float y10 = oacc[f][2] * inv1, y11 = oacc[f][3] * inv1;
        __half h00 = __float2half_rn(y00), h01 = __float2half_rn(y01);
        __half h10 = __float2half_rn(y10), h11 = __float2half_rn(y11);
        *(__half2*)(ch + base0 + col) = __half2(h00, h01);
        *(__half2*)(cl + base0 + col) = __half2(__float2half_rn(y00 - __half2float(h00)),
                                                __float2half_rn(y01 - __half2float(h01)));
        *(__half2*)(ch + base1 + col) = __half2(h10, h11);
        *(__half2*)(cl + base1 + col) = __half2(__float2half_rn(y10 - __half2float(h10)),
                                                __float2half_rn(y11 - __half2float(h11)));
    }
}

// ================= launch =================
extern "C" void kernel_launch(void* const* d_in, const int* in_sizes, int n_in,
                              void* d_out, int out_size)
{
    const float* x   = (const float*)d_in[0];
    const int*   pos = (const int*)d_in[1];
    const float* wq  = (const float*)d_in[2];
    const float* wk  = (const float*)d_in[3];
    const float* wv  = (const float*)d_in[4];
    const float* wo  = (const float*)d_in[5];
    float* out = (float*)d_out;

    float *Qp, *Kp, *Vp;
    cudaGetSymbolAddress((void**)&Qp, g_Q);
    cudaGetSymbolAddress((void**)&Kp, g_K);
    cudaGetSymbolAddress((void**)&Vp, g_V);

    __half *xh, *xl, *wq16, *wk16, *wv16, *wo16, *ch, *cl;
    cudaGetSymbolAddress((void**)&xh,   g_xh16);
    cudaGetSymbolAddress((void**)&xl,   g_xl16);
    cudaGetSymbolAddress((void**)&wq16, g_wq16);
    cudaGetSymbolAddress((void**)&wk16, g_wk16);
    cudaGetSymbolAddress((void**)&wv16, g_wv16);
    cudaGetSymbolAddress((void**)&wo16, g_wo16);
    cudaGetSymbolAddress((void**)&ch,   g_ch16);
    cudaGetSymbolAddress((void**)&cl,   g_cl16);

    __half *qah, *qal, *ka, *vth, *vtl;
    cudaGetSymbolAddress((void**)&qah, g_qah);
    cudaGetSymbolAddress((void**)&qal, g_qal);
    cudaGetSymbolAddress((void**)&ka,  g_ka16);
    cudaGetSymbolAddress((void**)&vth, g_vth16);
    cudaGetSymbolAddress((void**)&vtl, g_vtl16);

    cudaFuncSetAttribute(gemm_qkv2, cudaFuncAttributeMaxDynamicSharedMemorySize, GEMM2_SMEM);
    cudaFuncSetAttribute(gemm_o2, cudaFuncAttributeMaxDynamicSharedMemorySize, GEMM2_SMEM);
    cudaFuncSetAttribute(flash_mma, cudaFuncAttributeMaxDynamicSharedMemorySize, FA3_SMEM);

    // fp16 conversions: x split hi/lo; weights single fp16
    split_fp16<<<(4096 * 2048 / 4) / 256, 256>>>(x, xh, xl, 4096 * 2048 / 4);
    conv_fp16<<<(2048 * 2048 / 4) / 256, 256>>>(wq, wq16, 2048 * 2048 / 4);
    conv_fp16<<<(512  * 2048 / 4) / 256, 256>>>(wk, wk16, 512 * 2048 / 4);
    conv_fp16<<<(512  * 2048 / 4) / 256, 256>>>(wv, wv16, 512 * 2048 / 4);
    conv_fp16<<<(2048 * 2048 / 4) / 256, 256>>>(wo, wo16, 2048 * 2048 / 4);

    // fused QKV projection (fp16 2-pass tensor cores)
    gemm_qkv2<<<dim3(24, 32), 256, GEMM2_SMEM>>>(xh, xl, wq16, wk16, wv16, Qp, Kp, Vp);

    // RoPE -> fp16 head-major (Q hi/lo pre-scaled; K single); V -> transposed fp16 hi/lo
    rope_q_f16<<<16384, 256>>>(Qp, pos, qah, qal);
    rope_k_f16<<<4096, 256>>>(Kp, pos, ka);
    prep_v16<<<dim3(32, 4, 2), 256>>>(Vp, vth, vtl);

    // causal GQA attention (fp16 2-pass); epilogue writes fp16 hi/lo ctx
    flash_mma<<<dim3(16, 16, 2), 256, FA3_SMEM>>>(qah, qal, ka, vth, vtl, ch, cl);

    // O projection (fp16 2-pass tensor cores)
    gemm_o2<<<dim3(16, 32), 256, GEMM2_SMEM>>>(ch, cl, wo16, out, 2048, 2048);
}